// round 1
// baseline (speedup 1.0000x reference)
#include <cuda_runtime.h>
#include <cuda_bf16.h>

// Problem shapes
#define BB 32
#define LL 48
#define DD 768
#define TT 32
#define VV 30522
#define HH 768

#define OUT_TEXT_ELEMS ((long)BB * LL * VV)          // 46,881,792
#define OUT_IOU_ELEMS  ((long)BB * 3 * TT * (TT+1))  // 101,376
#define OUT_IOU_BASE   (OUT_TEXT_ELEMS)
#define OUT_MASK_BASE  (OUT_TEXT_ELEMS + OUT_IOU_ELEMS)

// Scratch (device globals; no allocations allowed)
__device__ float g_h1[(long)BB * LL * HH];            // relu(ht @ w_t1 + b_t1)
__device__ float g_proj[3L * BB * (TT + 1) * HH];     // [chunk s/c/e][b*33+pos][H]

// ---------------------------------------------------------------------------
// Generic tiled SGEMM: C = op(A(MxK,row) * B(KxN,row) + bias), optional relu.
// z-batched via strides (sA/sB/sC in elements). K must be a multiple of 8.
// BM=128, BN=128, BK=8, 256 threads, 8x8 per thread.
// ---------------------------------------------------------------------------
#define BM 128
#define BN 128
#define BKK 8

__global__ __launch_bounds__(256) void sgemm_k(
    const float* __restrict__ A, const float* __restrict__ Bm,
    const float* __restrict__ bias, float* __restrict__ C,
    int M, int N, int K,
    long sA, long sB, long sC, int do_relu)
{
    A  += (long)blockIdx.z * sA;
    Bm += (long)blockIdx.z * sB;
    C  += (long)blockIdx.z * sC;

    __shared__ float As[BKK][BM + 4];
    __shared__ float Bs[BKK][BN + 4];

    const int tid = threadIdx.x;
    const int tx = tid & 15;       // N direction (16 * TN=8 -> 128)
    const int ty = tid >> 4;       // M direction (16 * TM=8 -> 128)
    const int row0 = blockIdx.y * BM;
    const int col0 = blockIdx.x * BN;

    float acc[8][8];
#pragma unroll
    for (int i = 0; i < 8; i++)
#pragma unroll
        for (int j = 0; j < 8; j++) acc[i][j] = 0.f;

    for (int k0 = 0; k0 < K; k0 += BKK) {
        // Load A tile (BM x BK), store transposed into As[k][m]
#pragma unroll
        for (int i = 0; i < 4; i++) {
            int idx = tid + i * 256;
            int r = idx >> 3;       // 0..127 (M)
            int c = idx & 7;        // 0..7   (K)
            int gr = row0 + r;
            As[c][r] = (gr < M) ? A[(long)gr * K + (k0 + c)] : 0.f;
        }
        // Load B tile (BK x BN)
#pragma unroll
        for (int i = 0; i < 4; i++) {
            int idx = tid + i * 256;
            int r = idx >> 7;       // 0..7   (K)
            int c = idx & 127;      // 0..127 (N)
            int gc = col0 + c;
            Bs[r][c] = (gc < N) ? Bm[(long)(k0 + r) * N + gc] : 0.f;
        }
        __syncthreads();

#pragma unroll
        for (int kk = 0; kk < BKK; kk++) {
            float4 a0 = *(const float4*)&As[kk][ty * 8];
            float4 a1 = *(const float4*)&As[kk][ty * 8 + 4];
            float4 b0 = *(const float4*)&Bs[kk][tx * 8];
            float4 b1 = *(const float4*)&Bs[kk][tx * 8 + 4];
            float a[8] = {a0.x, a0.y, a0.z, a0.w, a1.x, a1.y, a1.z, a1.w};
            float b[8] = {b0.x, b0.y, b0.z, b0.w, b1.x, b1.y, b1.z, b1.w};
#pragma unroll
            for (int i = 0; i < 8; i++)
#pragma unroll
                for (int j = 0; j < 8; j++)
                    acc[i][j] = fmaf(a[i], b[j], acc[i][j]);
        }
        __syncthreads();
    }

#pragma unroll
    for (int i = 0; i < 8; i++) {
        int gr = row0 + ty * 8 + i;
        if (gr >= M) continue;
#pragma unroll
        for (int j = 0; j < 8; j++) {
            int gc = col0 + tx * 8 + j;
            if (gc >= N) continue;
            float v = acc[i][j];
            if (bias) v += bias[gc];
            if (do_relu) v = fmaxf(v, 0.f);
            C[(long)gr * N + gc] = v;
        }
    }
}

// ---------------------------------------------------------------------------
// IoU combine: h = relu(Ps[b,s] + Pc[b,(s+e)/2] + Pe[b,e] + b_i1)
// out_iou[b,k,s,e] = h . w_i2[:,k] + b_i2[k]
// One block of 256 threads per (b,s,e) cell. 32*32*33 = 33792 blocks.
// ---------------------------------------------------------------------------
__global__ __launch_bounds__(256) void iou_combine_k(
    const float* __restrict__ P, const float* __restrict__ b1,
    const float* __restrict__ w2, const float* __restrict__ b2,
    float* __restrict__ out)
{
    const int idx = blockIdx.x;
    const int e = idx % 33;
    const int s = (idx / 33) % 32;
    const int b = idx / (33 * 32);
    const int c = (s + e) >> 1;

    const long rowstride = (long)BB * 33 * HH;
    const float* ps = P + (long)(b * 33 + s) * HH;
    const float* pc = P + rowstride + (long)(b * 33 + c) * HH;
    const float* pe = P + 2 * rowstride + (long)(b * 33 + e) * HH;

    float k0 = 0.f, k1 = 0.f, k2 = 0.f;
    for (int h = threadIdx.x; h < HH; h += 256) {
        float v = ps[h] + pc[h] + pe[h] + b1[h];
        v = fmaxf(v, 0.f);
        k0 = fmaf(v, w2[h * 3 + 0], k0);
        k1 = fmaf(v, w2[h * 3 + 1], k1);
        k2 = fmaf(v, w2[h * 3 + 2], k2);
    }
#pragma unroll
    for (int off = 16; off; off >>= 1) {
        k0 += __shfl_xor_sync(0xFFFFFFFFu, k0, off);
        k1 += __shfl_xor_sync(0xFFFFFFFFu, k1, off);
        k2 += __shfl_xor_sync(0xFFFFFFFFu, k2, off);
    }
    __shared__ float red[3][8];
    const int lane = threadIdx.x & 31, w = threadIdx.x >> 5;
    if (lane == 0) { red[0][w] = k0; red[1][w] = k1; red[2][w] = k2; }
    __syncthreads();
    if (threadIdx.x == 0) {
        float r0 = b2[0], r1 = b2[1], r2 = b2[2];
#pragma unroll
        for (int i = 0; i < 8; i++) { r0 += red[0][i]; r1 += red[1][i]; r2 += red[2][i]; }
        // out_iou[b][k][s][e] with k-major stride 32*33
        long base = OUT_IOU_BASE + ((long)b * 3) * (32 * 33) + (long)s * 33 + e;
        out[base + 0 * 32 * 33] = r0;
        out[base + 1 * 32 * 33] = r1;
        out[base + 2 * 32 * 33] = r2;
    }
}

// ---------------------------------------------------------------------------
// Mask map (32 x 33), computed analytically.
// ---------------------------------------------------------------------------
__global__ void mask_k(float* __restrict__ out)
{
    int idx = blockIdx.x * blockDim.x + threadIdx.x;
    if (idx >= 32 * 33) return;
    int i = idx / 33, j = idx % 33;
    float v = 0.f;
    int hi = (i + 17 < 33) ? (i + 17) : 33;
    if (j >= i + 1 && j < hi) v = 1.f;
    if (i < 16 && (i & 1) == 0 && j >= 18 + i && ((j - 18 - i) & 1) == 0) v = 1.f;
    out[OUT_MASK_BASE + idx] = v;
}

// ---------------------------------------------------------------------------
extern "C" void kernel_launch(void* const* d_in, const int* in_sizes, int n_in,
                              void* d_out, int out_size)
{
    const float* ht   = (const float*)d_in[0]; // (32,48,768)
    const float* hc   = (const float*)d_in[1]; // (32,33,768)
    const float* w_t1 = (const float*)d_in[2]; // (768,768)
    const float* b_t1 = (const float*)d_in[3]; // (768)
    const float* w_t2 = (const float*)d_in[4]; // (768,30522)
    const float* b_t2 = (const float*)d_in[5]; // (30522)
    const float* w_i1 = (const float*)d_in[6]; // (2304,768)
    const float* b_i1 = (const float*)d_in[7]; // (768)
    const float* w_i2 = (const float*)d_in[8]; // (768,3)
    const float* b_i2 = (const float*)d_in[9]; // (3)
    float* out = (float*)d_out;

    float* h1;   cudaGetSymbolAddress((void**)&h1, g_h1);
    float* proj; cudaGetSymbolAddress((void**)&proj, g_proj);

    const int Mtxt = BB * LL;      // 1536
    const int Mobj = BB * (TT+1);  // 1056

    // 1) h1 = relu(ht @ w_t1 + b_t1)
    {
        dim3 grid((HH + BN - 1) / BN, (Mtxt + BM - 1) / BM, 1);
        sgemm_k<<<grid, 256>>>(ht, w_t1, b_t1, h1, Mtxt, HH, DD, 0, 0, 0, 1);
    }
    // 2) projections of hc through the three 768x768 chunks of w_i1 (z-batched)
    {
        dim3 grid((HH + BN - 1) / BN, (Mobj + BM - 1) / BM, 3);
        sgemm_k<<<grid, 256>>>(hc, w_i1, nullptr, proj, Mobj, HH, DD,
                               0, (long)DD * HH, (long)Mobj * HH, 0);
    }
    // 3) logits_text = h1 @ w_t2 + b_t2  (the big one)
    {
        dim3 grid((VV + BN - 1) / BN, (Mtxt + BM - 1) / BM, 1);
        sgemm_k<<<grid, 256>>>(h1, w_t2, b_t2, out, Mtxt, VV, DD, 0, 0, 0, 0);
    }
    // 4) IoU combine + tiny contraction
    iou_combine_k<<<BB * TT * (TT + 1), 256>>>(proj, b_i1, w_i2, b_i2, out);
    // 5) mask map
    mask_k<<<(32 * 33 + 255) / 256, 256>>>(out);
}

// round 3
// speedup vs baseline: 2.3735x; 2.3735x over previous
#include <cuda_runtime.h>
#include <cuda_bf16.h>
#include <cstdint>

// Problem shapes
#define BB 32
#define LL 48
#define DD 768
#define TT 32
#define VV 30522
#define HH 768
#define NPAD 30592  // 239 * 128

#define OUT_TEXT_ELEMS ((long)BB * LL * VV)          // 46,881,792
#define OUT_IOU_ELEMS  ((long)BB * 3 * TT * (TT+1))  // 101,376
#define OUT_IOU_BASE   (OUT_TEXT_ELEMS)
#define OUT_MASK_BASE  (OUT_TEXT_ELEMS + OUT_IOU_ELEMS)

// Scratch (device globals; no allocations allowed)
__device__ float g_h1[(long)BB * LL * HH];            // relu(ht @ w_t1 + b_t1)
__device__ float g_proj[3L * BB * (TT + 1) * HH];     // [chunk s/c/e][b*33+pos][H]
__device__ __nv_bfloat16 g_Ahi[(long)BB * LL * DD];
__device__ __nv_bfloat16 g_Alo[(long)BB * LL * DD];
__device__ __nv_bfloat16 g_Bthi[(long)NPAD * DD];     // w_t2 transposed (N x K), padded
__device__ __nv_bfloat16 g_Btlo[(long)NPAD * DD];

// ---------------------------------------------------------------------------
// helpers
// ---------------------------------------------------------------------------
__device__ __forceinline__ uint32_t smem_u32(const void* p) {
    uint32_t a;
    asm("{ .reg .u64 t; cvta.to.shared.u64 t, %1; cvt.u32.u64 %0, t; }" : "=r"(a) : "l"(p));
    return a;
}
__device__ __forceinline__ void cp_async16(uint32_t saddr, const void* gptr) {
    asm volatile("cp.async.cg.shared.global [%0], [%1], 16;" :: "r"(saddr), "l"(gptr));
}
#define CP_COMMIT()  asm volatile("cp.async.commit_group;" ::: "memory")
#define CP_WAIT1()   asm volatile("cp.async.wait_group 1;" ::: "memory")

#define SWZ(o) ((o) ^ (((o) >> 3) & 0x70))

__device__ __forceinline__ void ldsm_x4(uint32_t addr, uint32_t& r0, uint32_t& r1,
                                        uint32_t& r2, uint32_t& r3) {
    asm volatile("ldmatrix.sync.aligned.m8n8.x4.shared.b16 {%0,%1,%2,%3}, [%4];"
                 : "=r"(r0), "=r"(r1), "=r"(r2), "=r"(r3) : "r"(addr));
}
__device__ __forceinline__ void mma16816(float* d, const uint32_t* a, const uint32_t* b) {
    asm volatile(
        "mma.sync.aligned.m16n8k16.row.col.f32.bf16.bf16.f32 "
        "{%0,%1,%2,%3}, {%4,%5,%6,%7}, {%8,%9}, {%0,%1,%2,%3};"
        : "+f"(d[0]), "+f"(d[1]), "+f"(d[2]), "+f"(d[3])
        : "r"(a[0]), "r"(a[1]), "r"(a[2]), "r"(a[3]), "r"(b[0]), "r"(b[1]));
}

// ---------------------------------------------------------------------------
// bf16 HMMA split-GEMM: out[m][n] = sum_k A[m][k]*B[n][k] + bias, fp32 out.
// 3 passes over K (hi*hi, lo*hi, hi*lo) accumulated in registers.
// Tile 128x128, BK=64 bf16 (128B rows, SW128), cp.async double buffer.
// 8 warps: 2 (M) x 4 (N); warp tile 64x32.
// grid = (NPAD/128, 1536/128), 256 threads.
// ---------------------------------------------------------------------------
#define NCHUNK 36  // 3 passes * 12 chunks of K=64

__global__ __launch_bounds__(256) void gemm3_mma(
    const __nv_bfloat16* __restrict__ Ahi, const __nv_bfloat16* __restrict__ Alo,
    const __nv_bfloat16* __restrict__ Bhi, const __nv_bfloat16* __restrict__ Blo,
    const float* __restrict__ bias, float* __restrict__ out)
{
    extern __shared__ char smem[];
    const uint32_t sbase = smem_u32(smem);
    const int tid  = threadIdx.x;
    const int wid  = tid >> 5;
    const int lane = tid & 31;
    const int row0 = blockIdx.y * 128;
    const int col0 = blockIdx.x * 128;
    const int wm = (wid & 1) * 64;   // warp M offset in tile
    const int wn = (wid >> 1) * 32;  // warp N offset in tile

    float acc[4][4][4];  // [mf][nf][reg]
#pragma unroll
    for (int i = 0; i < 4; i++)
#pragma unroll
        for (int j = 0; j < 4; j++)
#pragma unroll
            for (int r = 0; r < 4; r++) acc[i][j][r] = 0.f;

#define LOAD_CHUNK(KC)                                                          \
    {                                                                           \
        int pass = (KC) / 12;                                                   \
        int kk = ((KC) - pass * 12) * 64;                                       \
        const __nv_bfloat16* Ap = (pass == 1) ? Alo : Ahi;                      \
        const __nv_bfloat16* Bp = (pass == 2) ? Blo : Bhi;                      \
        uint32_t sA = sbase + ((KC) & 1) * 32768;                               \
        uint32_t sB = sA + 16384;                                               \
        _Pragma("unroll")                                                       \
        for (int i = 0; i < 4; i++) {                                           \
            int idx = tid + (i << 8);                                           \
            int m = idx >> 3, j = idx & 7;                                      \
            cp_async16(sA + SWZ(m * 128 + j * 16),                              \
                       Ap + (size_t)(row0 + m) * DD + kk + j * 8);              \
            cp_async16(sB + SWZ(m * 128 + j * 16),                              \
                       Bp + (size_t)(col0 + m) * DD + kk + j * 8);              \
        }                                                                       \
        CP_COMMIT();                                                            \
    }

    LOAD_CHUNK(0);
    LOAD_CHUNK(1);

    // lane-derived ldmatrix row/byte offsets
    const int a_m  = lane & 15;             // row within 16
    const int a_kb = (lane >> 4) << 4;      // 0 or 16 bytes
    const int b_n  = (lane & 7) + ((lane >> 4) << 3);  // row within 16
    const int b_kb = ((lane >> 3) & 1) << 4;           // 0 or 16 bytes

    for (int kc = 0; kc < NCHUNK; kc++) {
        CP_WAIT1();
        __syncthreads();
        const uint32_t sA = sbase + (kc & 1) * 32768;
        const uint32_t sB = sA + 16384;

#pragma unroll
        for (int k16 = 0; k16 < 4; k16++) {
            const int kb = k16 * 32;
            uint32_t a[4][4], b[2][4];
#pragma unroll
            for (int mf = 0; mf < 4; mf++)
                ldsm_x4(sA + SWZ((wm + mf * 16 + a_m) * 128 + kb + a_kb),
                        a[mf][0], a[mf][1], a[mf][2], a[mf][3]);
#pragma unroll
            for (int np = 0; np < 2; np++)
                ldsm_x4(sB + SWZ((wn + np * 16 + b_n) * 128 + kb + b_kb),
                        b[np][0], b[np][1], b[np][2], b[np][3]);
#pragma unroll
            for (int mf = 0; mf < 4; mf++) {
#pragma unroll
                for (int nf = 0; nf < 4; nf++) {
                    uint32_t bb[2] = { b[nf >> 1][(nf & 1) * 2],
                                       b[nf >> 1][(nf & 1) * 2 + 1] };
                    mma16816(acc[mf][nf], a[mf], bb);
                }
            }
        }
        __syncthreads();
        if (kc + 2 < NCHUNK) LOAD_CHUNK(kc + 2);
    }
#undef LOAD_CHUNK

    // epilogue: d0,d1 at (m=lane/4, n=(lane%4)*2), d2,d3 at m+8
    const int em = lane >> 2;
    const int en = (lane & 3) * 2;
#pragma unroll
    for (int mf = 0; mf < 4; mf++) {
#pragma unroll
        for (int half = 0; half < 2; half++) {
            int gr = row0 + wm + mf * 16 + em + half * 8;
            float* orow = out + (size_t)gr * VV;
#pragma unroll
            for (int nf = 0; nf < 4; nf++) {
                int gc = col0 + wn + nf * 8 + en;
                if (gc + 1 < VV) {
                    float2 v;
                    v.x = acc[mf][nf][half * 2]     + __ldg(bias + gc);
                    v.y = acc[mf][nf][half * 2 + 1] + __ldg(bias + gc + 1);
                    *(float2*)(orow + gc) = v;
                } else if (gc < VV) {
                    orow[gc] = acc[mf][nf][half * 2] + __ldg(bias + gc);
                }
            }
        }
    }
}

// ---------------------------------------------------------------------------
// fp32 -> bf16 hi/lo split (elementwise)
// ---------------------------------------------------------------------------
__global__ void split_k(const float* __restrict__ in, __nv_bfloat16* __restrict__ hi,
                        __nv_bfloat16* __restrict__ lo, long n)
{
    long i = (long)blockIdx.x * blockDim.x + threadIdx.x;
    if (i >= n) return;
    float x = in[i];
    __nv_bfloat16 h = __float2bfloat16(x);
    float hf = __bfloat162float(h);
    hi[i] = h;
    lo[i] = __float2bfloat16(x - hf);
}

// ---------------------------------------------------------------------------
// transpose + split: in (K x N) fp32 -> hi/lo (NPAD x K) bf16, zero-padded rows
// ---------------------------------------------------------------------------
__global__ void tsplit_k(const float* __restrict__ in, __nv_bfloat16* __restrict__ hi,
                         __nv_bfloat16* __restrict__ lo, int K, int N)
{
    __shared__ float t[32][33];
    int n0 = blockIdx.x * 32, k0 = blockIdx.y * 32;
    int n = n0 + threadIdx.x, k = k0 + threadIdx.y;
    t[threadIdx.y][threadIdx.x] = (n < N) ? in[(long)k * N + n] : 0.f;
    __syncthreads();
    int orow = n0 + threadIdx.y, ocol = k0 + threadIdx.x;
    float x = t[threadIdx.x][threadIdx.y];
    __nv_bfloat16 h = __float2bfloat16(x);
    float hf = __bfloat162float(h);
    hi[(long)orow * K + ocol] = h;
    lo[(long)orow * K + ocol] = __float2bfloat16(x - hf);
}

// ---------------------------------------------------------------------------
// fp32 tiled SGEMM (kept for the small GEMMs)
// ---------------------------------------------------------------------------
#define BM 128
#define BN 128
#define BKK 8

__global__ __launch_bounds__(256) void sgemm_k(
    const float* __restrict__ A, const float* __restrict__ Bm,
    const float* __restrict__ bias, float* __restrict__ C,
    int M, int N, int K,
    long sA, long sB, long sC, int do_relu)
{
    A  += (long)blockIdx.z * sA;
    Bm += (long)blockIdx.z * sB;
    C  += (long)blockIdx.z * sC;

    __shared__ float As[BKK][BM + 4];
    __shared__ float Bs[BKK][BN + 4];

    const int tid = threadIdx.x;
    const int tx = tid & 15;
    const int ty = tid >> 4;
    const int row0 = blockIdx.y * BM;
    const int col0 = blockIdx.x * BN;

    float acc[8][8];
#pragma unroll
    for (int i = 0; i < 8; i++)
#pragma unroll
        for (int j = 0; j < 8; j++) acc[i][j] = 0.f;

    for (int k0 = 0; k0 < K; k0 += BKK) {
#pragma unroll
        for (int i = 0; i < 4; i++) {
            int idx = tid + i * 256;
            int r = idx >> 3;
            int c = idx & 7;
            int gr = row0 + r;
            As[c][r] = (gr < M) ? A[(long)gr * K + (k0 + c)] : 0.f;
        }
#pragma unroll
        for (int i = 0; i < 4; i++) {
            int idx = tid + i * 256;
            int r = idx >> 7;
            int c = idx & 127;
            int gc = col0 + c;
            Bs[r][c] = (gc < N) ? Bm[(long)(k0 + r) * N + gc] : 0.f;
        }
        __syncthreads();

#pragma unroll
        for (int kk = 0; kk < BKK; kk++) {
            float4 a0 = *(const float4*)&As[kk][ty * 8];
            float4 a1 = *(const float4*)&As[kk][ty * 8 + 4];
            float4 b0 = *(const float4*)&Bs[kk][tx * 8];
            float4 b1 = *(const float4*)&Bs[kk][tx * 8 + 4];
            float a[8] = {a0.x, a0.y, a0.z, a0.w, a1.x, a1.y, a1.z, a1.w};
            float b[8] = {b0.x, b0.y, b0.z, b0.w, b1.x, b1.y, b1.z, b1.w};
#pragma unroll
            for (int i = 0; i < 8; i++)
#pragma unroll
                for (int j = 0; j < 8; j++)
                    acc[i][j] = fmaf(a[i], b[j], acc[i][j]);
        }
        __syncthreads();
    }

#pragma unroll
    for (int i = 0; i < 8; i++) {
        int gr = row0 + ty * 8 + i;
        if (gr >= M) continue;
#pragma unroll
        for (int j = 0; j < 8; j++) {
            int gc = col0 + tx * 8 + j;
            if (gc >= N) continue;
            float v = acc[i][j];
            if (bias) v += bias[gc];
            if (do_relu) v = fmaxf(v, 0.f);
            C[(long)gr * N + gc] = v;
        }
    }
}

// ---------------------------------------------------------------------------
// IoU combine
// ---------------------------------------------------------------------------
__global__ __launch_bounds__(256) void iou_combine_k(
    const float* __restrict__ P, const float* __restrict__ b1,
    const float* __restrict__ w2, const float* __restrict__ b2,
    float* __restrict__ out)
{
    const int idx = blockIdx.x;
    const int e = idx % 33;
    const int s = (idx / 33) % 32;
    const int b = idx / (33 * 32);
    const int c = (s + e) >> 1;

    const long rowstride = (long)BB * 33 * HH;
    const float* ps = P + (long)(b * 33 + s) * HH;
    const float* pc = P + rowstride + (long)(b * 33 + c) * HH;
    const float* pe = P + 2 * rowstride + (long)(b * 33 + e) * HH;

    float k0 = 0.f, k1 = 0.f, k2 = 0.f;
    for (int h = threadIdx.x; h < HH; h += 256) {
        float v = ps[h] + pc[h] + pe[h] + b1[h];
        v = fmaxf(v, 0.f);
        k0 = fmaf(v, w2[h * 3 + 0], k0);
        k1 = fmaf(v, w2[h * 3 + 1], k1);
        k2 = fmaf(v, w2[h * 3 + 2], k2);
    }
#pragma unroll
    for (int off = 16; off; off >>= 1) {
        k0 += __shfl_xor_sync(0xFFFFFFFFu, k0, off);
        k1 += __shfl_xor_sync(0xFFFFFFFFu, k1, off);
        k2 += __shfl_xor_sync(0xFFFFFFFFu, k2, off);
    }
    __shared__ float red[3][8];
    const int lane = threadIdx.x & 31, w = threadIdx.x >> 5;
    if (lane == 0) { red[0][w] = k0; red[1][w] = k1; red[2][w] = k2; }
    __syncthreads();
    if (threadIdx.x == 0) {
        float r0 = b2[0], r1 = b2[1], r2 = b2[2];
#pragma unroll
        for (int i = 0; i < 8; i++) { r0 += red[0][i]; r1 += red[1][i]; r2 += red[2][i]; }
        long base = OUT_IOU_BASE + ((long)b * 3) * (32 * 33) + (long)s * 33 + e;
        out[base + 0 * 32 * 33] = r0;
        out[base + 1 * 32 * 33] = r1;
        out[base + 2 * 32 * 33] = r2;
    }
}

// ---------------------------------------------------------------------------
// Mask map
// ---------------------------------------------------------------------------
__global__ void mask_k(float* __restrict__ out)
{
    int idx = blockIdx.x * blockDim.x + threadIdx.x;
    if (idx >= 32 * 33) return;
    int i = idx / 33, j = idx % 33;
    float v = 0.f;
    int hi = (i + 17 < 33) ? (i + 17) : 33;
    if (j >= i + 1 && j < hi) v = 1.f;
    if (i < 16 && (i & 1) == 0 && j >= 18 + i && ((j - 18 - i) & 1) == 0) v = 1.f;
    out[OUT_MASK_BASE + idx] = v;
}

// ---------------------------------------------------------------------------
extern "C" void kernel_launch(void* const* d_in, const int* in_sizes, int n_in,
                              void* d_out, int out_size)
{
    const float* ht   = (const float*)d_in[0];
    const float* hc   = (const float*)d_in[1];
    const float* w_t1 = (const float*)d_in[2];
    const float* b_t1 = (const float*)d_in[3];
    const float* w_t2 = (const float*)d_in[4];
    const float* b_t2 = (const float*)d_in[5];
    const float* w_i1 = (const float*)d_in[6];
    const float* b_i1 = (const float*)d_in[7];
    const float* w_i2 = (const float*)d_in[8];
    const float* b_i2 = (const float*)d_in[9];
    float* out = (float*)d_out;

    float* h1;   cudaGetSymbolAddress((void**)&h1, g_h1);
    float* proj; cudaGetSymbolAddress((void**)&proj, g_proj);
    __nv_bfloat16 *Ahi, *Alo, *Bhi, *Blo;
    cudaGetSymbolAddress((void**)&Ahi, g_Ahi);
    cudaGetSymbolAddress((void**)&Alo, g_Alo);
    cudaGetSymbolAddress((void**)&Bhi, g_Bthi);
    cudaGetSymbolAddress((void**)&Blo, g_Btlo);

    cudaFuncSetAttribute(gemm3_mma, cudaFuncAttributeMaxDynamicSharedMemorySize, 65536);

    const int Mtxt = BB * LL;       // 1536
    const int Mobj = BB * (TT + 1); // 1056

    // 0) transpose+split w_t2 -> (NPAD x 768) bf16 hi/lo
    {
        dim3 grid(NPAD / 32, DD / 32);
        tsplit_k<<<grid, dim3(32, 32)>>>(w_t2, Bhi, Blo, DD, VV);
    }
    // 1) h1 = relu(ht @ w_t1 + b_t1)  (fp32)
    {
        dim3 grid((HH + BN - 1) / BN, (Mtxt + BM - 1) / BM, 1);
        sgemm_k<<<grid, 256>>>(ht, w_t1, b_t1, h1, Mtxt, HH, DD, 0, 0, 0, 1);
    }
    // 2) split h1 -> bf16 hi/lo
    {
        long n = (long)Mtxt * HH;
        split_k<<<(int)((n + 255) / 256), 256>>>(h1, Ahi, Alo, n);
    }
    // 3) logits_text = h1 @ w_t2 + b_t2  (HMMA bf16 3-term split)
    {
        dim3 grid(NPAD / 128, Mtxt / 128);
        gemm3_mma<<<grid, 256, 65536>>>(Ahi, Alo, Bhi, Blo, b_t2, out);
    }
    // 4) projections of hc (fp32)
    {
        dim3 grid((HH + BN - 1) / BN, (Mobj + BM - 1) / BM, 3);
        sgemm_k<<<grid, 256>>>(hc, w_i1, nullptr, proj, Mobj, HH, DD,
                               0, (long)DD * HH, (long)Mobj * HH, 0);
    }
    // 5) IoU combine
    iou_combine_k<<<BB * TT * (TT + 1), 256>>>(proj, b_i1, w_i2, b_i2, out);
    // 6) mask map
    mask_k<<<(32 * 33 + 255) / 256, 256>>>(out);
}

// round 4
// speedup vs baseline: 2.9540x; 1.2446x over previous
#include <cuda_runtime.h>
#include <cuda_bf16.h>
#include <cstdint>

// Problem shapes
#define BB 32
#define LL 48
#define DD 768
#define TT 32
#define VV 30522
#define HH 768
#define NPAD 30592   // 239 * 128
#define MPROJ 1056   // 32*33
#define MPROJP 1152  // 9*128 padded
#define MTXT 1536

#define OUT_TEXT_ELEMS ((long)BB * LL * VV)
#define OUT_IOU_ELEMS  ((long)BB * 3 * TT * (TT+1))
#define OUT_IOU_BASE   (OUT_TEXT_ELEMS)
#define OUT_MASK_BASE  (OUT_TEXT_ELEMS + OUT_IOU_ELEMS)

// Scratch (device globals; no allocations allowed)
__device__ float g_proj[3L * MPROJP * HH];
__device__ __nv_bfloat16 g_Athi[(long)MTXT * DD],  g_Atlo[(long)MTXT * DD];   // ht split
__device__ __nv_bfloat16 g_Achi[(long)MPROJ * DD], g_Aclo[(long)MPROJ * DD];  // hc split
__device__ __nv_bfloat16 g_H1hi[(long)MTXT * HH],  g_H1lo[(long)MTXT * HH];   // gemm1 out
__device__ __nv_bfloat16 g_Bw1hi[(long)HH * DD],   g_Bw1lo[(long)HH * DD];    // w_t1^T
__device__ __nv_bfloat16 g_Bi1hi[3L * HH * DD],    g_Bi1lo[3L * HH * DD];     // w_i1^T chunks
__device__ __nv_bfloat16 g_Bw2hi[(long)NPAD * DD], g_Bw2lo[(long)NPAD * DD];  // w_t2^T

// ---------------------------------------------------------------------------
// helpers
// ---------------------------------------------------------------------------
__device__ __forceinline__ uint32_t smem_u32(const void* p) {
    uint32_t a;
    asm("{ .reg .u64 t; cvta.to.shared.u64 t, %1; cvt.u32.u64 %0, t; }" : "=r"(a) : "l"(p));
    return a;
}
__device__ __forceinline__ void cp_async16(uint32_t saddr, const void* gptr) {
    asm volatile("cp.async.cg.shared.global [%0], [%1], 16;" :: "r"(saddr), "l"(gptr));
}
__device__ __forceinline__ void cp_async16z(uint32_t saddr, const void* gptr, bool pred) {
    int sz = pred ? 16 : 0;
    asm volatile("cp.async.cg.shared.global [%0], [%1], 16, %2;"
                 :: "r"(saddr), "l"(gptr), "r"(sz));
}
#define CP_COMMIT()  asm volatile("cp.async.commit_group;" ::: "memory")
#define CP_WAIT2()   asm volatile("cp.async.wait_group 2;" ::: "memory")
#define CP_WAIT1()   asm volatile("cp.async.wait_group 1;" ::: "memory")
#define CP_WAIT0()   asm volatile("cp.async.wait_group 0;" ::: "memory")

#define SWZ(o) ((o) ^ (((o) >> 3) & 0x70))

__device__ __forceinline__ void ldsm_x4(uint32_t addr, uint32_t& r0, uint32_t& r1,
                                        uint32_t& r2, uint32_t& r3) {
    asm volatile("ldmatrix.sync.aligned.m8n8.x4.shared.b16 {%0,%1,%2,%3}, [%4];"
                 : "=r"(r0), "=r"(r1), "=r"(r2), "=r"(r3) : "r"(addr));
}
__device__ __forceinline__ void mma16816(float* d, const uint32_t* a, const uint32_t* b) {
    asm volatile(
        "mma.sync.aligned.m16n8k16.row.col.f32.bf16.bf16.f32 "
        "{%0,%1,%2,%3}, {%4,%5,%6,%7}, {%8,%9}, {%0,%1,%2,%3};"
        : "+f"(d[0]), "+f"(d[1]), "+f"(d[2]), "+f"(d[3])
        : "r"(a[0]), "r"(a[1]), "r"(a[2]), "r"(a[3]), "r"(b[0]), "r"(b[1]));
}

// ---------------------------------------------------------------------------
// Generic bf16 HMMA 3-pass split GEMM.  C = A*B^T (+bias); K=768.
// Tile 128x128, BK=64 bf16 (SW128), 3-stage cp.async pipeline, 256 thr.
// 8 warps: 2(M) x 4(N); warp tile 64x32.
// MODE 0: fp32 C (+bias), N clipped to Nclip.   (vocab GEMM)
// MODE 1: relu(acc+bias), write bf16 hi/lo pair. (text GEMM1)
// MODE 2: fp32 C, bias only when blockIdx.z==0. (projections)
// ---------------------------------------------------------------------------
#define NCHUNK 36  // 3 passes * 12 chunks of K=64

template<int MODE>
__global__ __launch_bounds__(256) void hgemm(
    const __nv_bfloat16* __restrict__ Ahi, const __nv_bfloat16* __restrict__ Alo,
    const __nv_bfloat16* __restrict__ Bhi, const __nv_bfloat16* __restrict__ Blo,
    const float* __restrict__ bias,
    float* __restrict__ Cf, __nv_bfloat16* __restrict__ Chi, __nv_bfloat16* __restrict__ Clo,
    int Mclip, int Nclip, long ldC, long zB, long zC)
{
    extern __shared__ char smem[];
    const uint32_t sbase = smem_u32(smem);
    const int tid  = threadIdx.x;
    const int wid  = tid >> 5;
    const int lane = tid & 31;
    const int row0 = blockIdx.y * 128;
    const int col0 = blockIdx.x * 128;
    const int wm = (wid & 1) * 64;
    const int wn = (wid >> 1) * 32;

    Bhi += (long)blockIdx.z * zB;
    Blo += (long)blockIdx.z * zB;
    if (MODE != 1) Cf += (long)blockIdx.z * zC;

    float acc[4][4][4];
#pragma unroll
    for (int i = 0; i < 4; i++)
#pragma unroll
        for (int j = 0; j < 4; j++)
#pragma unroll
            for (int r = 0; r < 4; r++) acc[i][j][r] = 0.f;

#define LOAD_CHUNK(KC)                                                          \
    {                                                                           \
        int pass = (KC) / 12;                                                   \
        int kk = ((KC) - pass * 12) * 64;                                       \
        const __nv_bfloat16* Ap = (pass == 1) ? Alo : Ahi;                      \
        const __nv_bfloat16* Bp = (pass == 2) ? Blo : Bhi;                      \
        uint32_t sA = sbase + ((KC) % 3) * 32768;                               \
        uint32_t sB = sA + 16384;                                               \
        _Pragma("unroll")                                                       \
        for (int i = 0; i < 4; i++) {                                           \
            int idx = tid + (i << 8);                                           \
            int m = idx >> 3, j = idx & 7;                                      \
            int grow = row0 + m;                                                \
            bool pa = grow < Mclip;                                             \
            cp_async16z(sA + SWZ(m * 128 + j * 16),                             \
                        Ap + (size_t)(pa ? grow : 0) * DD + kk + j * 8, pa);    \
            cp_async16(sB + SWZ(m * 128 + j * 16),                              \
                       Bp + (size_t)(col0 + m) * DD + kk + j * 8);              \
        }                                                                       \
        CP_COMMIT();                                                            \
    }

    LOAD_CHUNK(0);
    LOAD_CHUNK(1);
    LOAD_CHUNK(2);

    const int a_m  = lane & 15;
    const int a_kb = (lane >> 4) << 4;
    const int b_n  = (lane & 7) + ((lane >> 4) << 3);
    const int b_kb = ((lane >> 3) & 1) << 4;

    for (int kc = 0; kc < NCHUNK; kc++) {
        if (kc < NCHUNK - 2)      { CP_WAIT2(); }
        else if (kc == NCHUNK - 2) { CP_WAIT1(); }
        else                       { CP_WAIT0(); }
        __syncthreads();
        const uint32_t sA = sbase + (kc % 3) * 32768;
        const uint32_t sB = sA + 16384;

#pragma unroll
        for (int k16 = 0; k16 < 4; k16++) {
            const int kb = k16 * 32;
            uint32_t a[4][4], b[2][4];
#pragma unroll
            for (int mf = 0; mf < 4; mf++)
                ldsm_x4(sA + SWZ((wm + mf * 16 + a_m) * 128 + kb + a_kb),
                        a[mf][0], a[mf][1], a[mf][2], a[mf][3]);
#pragma unroll
            for (int np = 0; np < 2; np++)
                ldsm_x4(sB + SWZ((wn + np * 16 + b_n) * 128 + kb + b_kb),
                        b[np][0], b[np][1], b[np][2], b[np][3]);
#pragma unroll
            for (int mf = 0; mf < 4; mf++) {
#pragma unroll
                for (int nf = 0; nf < 4; nf++) {
                    uint32_t bb[2] = { b[nf >> 1][(nf & 1) * 2],
                                       b[nf >> 1][(nf & 1) * 2 + 1] };
                    mma16816(acc[mf][nf], a[mf], bb);
                }
            }
        }
        __syncthreads();
        if (kc + 3 < NCHUNK) LOAD_CHUNK(kc + 3);
    }
#undef LOAD_CHUNK

    // epilogue
    const int em = lane >> 2;
    const int en = (lane & 3) * 2;
    const bool bias_on = (MODE != 2) || (blockIdx.z == 0);
#pragma unroll
    for (int mf = 0; mf < 4; mf++) {
#pragma unroll
        for (int half = 0; half < 2; half++) {
            int gr = row0 + wm + mf * 16 + em + half * 8;
#pragma unroll
            for (int nf = 0; nf < 4; nf++) {
                int gc = col0 + wn + nf * 8 + en;
                float vx = acc[mf][nf][half * 2];
                float vy = acc[mf][nf][half * 2 + 1];
                if (MODE == 0) {
                    float* orow = Cf + (size_t)gr * ldC;
                    if (gc + 1 < Nclip) {
                        float2 v = { vx + __ldg(bias + gc), vy + __ldg(bias + gc + 1) };
                        *(float2*)(orow + gc) = v;
                    } else if (gc < Nclip) {
                        orow[gc] = vx + __ldg(bias + gc);
                    }
                } else if (MODE == 1) {
                    vx = fmaxf(vx + __ldg(bias + gc), 0.f);
                    vy = fmaxf(vy + __ldg(bias + gc + 1), 0.f);
                    __nv_bfloat162 h, l;
                    h.x = __float2bfloat16(vx);
                    h.y = __float2bfloat16(vy);
                    l.x = __float2bfloat16(vx - __bfloat162float(h.x));
                    l.y = __float2bfloat16(vy - __bfloat162float(h.y));
                    *(__nv_bfloat162*)(Chi + (size_t)gr * ldC + gc) = h;
                    *(__nv_bfloat162*)(Clo + (size_t)gr * ldC + gc) = l;
                } else {  // MODE 2
                    if (bias_on) { vx += __ldg(bias + gc); vy += __ldg(bias + gc + 1); }
                    float2 v = { vx, vy };
                    *(float2*)(Cf + (size_t)gr * ldC + gc) = v;
                }
            }
        }
    }
}

// ---------------------------------------------------------------------------
// fp32 -> bf16 hi/lo split (elementwise)
// ---------------------------------------------------------------------------
__global__ void split_k(const float* __restrict__ in, __nv_bfloat16* __restrict__ hi,
                        __nv_bfloat16* __restrict__ lo, long n)
{
    long i = (long)blockIdx.x * blockDim.x + threadIdx.x;
    if (i >= n) return;
    float x = in[i];
    __nv_bfloat16 h = __float2bfloat16(x);
    hi[i] = h;
    lo[i] = __float2bfloat16(x - __bfloat162float(h));
}

// ---------------------------------------------------------------------------
// transpose + split: in (K x N) fp32 -> hi/lo (Nout x K) bf16, zero-padded rows
// z-batched via strides.
// ---------------------------------------------------------------------------
__global__ void tsplit_k(const float* __restrict__ in, __nv_bfloat16* __restrict__ hi,
                         __nv_bfloat16* __restrict__ lo, int K, int N,
                         long inZ, long outZ)
{
    in += (long)blockIdx.z * inZ;
    hi += (long)blockIdx.z * outZ;
    lo += (long)blockIdx.z * outZ;
    __shared__ float t[32][33];
    int n0 = blockIdx.x * 32, k0 = blockIdx.y * 32;
    int n = n0 + threadIdx.x, k = k0 + threadIdx.y;
    t[threadIdx.y][threadIdx.x] = (n < N) ? in[(long)k * N + n] : 0.f;
    __syncthreads();
    int orow = n0 + threadIdx.y, ocol = k0 + threadIdx.x;
    float x = t[threadIdx.x][threadIdx.y];
    __nv_bfloat16 h = __float2bfloat16(x);
    hi[(long)orow * K + ocol] = h;
    lo[(long)orow * K + ocol] = __float2bfloat16(x - __bfloat162float(h));
}

// ---------------------------------------------------------------------------
// IoU combine: b_i1 already folded into chunk-0 projection.
// 192 threads: thread t handles float4 at h = 4t. One block per (b,s,e).
// ---------------------------------------------------------------------------
__global__ __launch_bounds__(192) void iou_combine_k(
    const float* __restrict__ P, const float* __restrict__ w2,
    const float* __restrict__ b2, float* __restrict__ out)
{
    const int idx = blockIdx.x;
    const int e = idx % 33;
    const int s = (idx / 33) % 32;
    const int b = idx / (33 * 32);
    const int c = (s + e) >> 1;

    const long CS = (long)MPROJP * HH;
    const int t = threadIdx.x;
    const float4* ps = (const float4*)(P + (long)(b * 33 + s) * HH);
    const float4* pc = (const float4*)(P + CS + (long)(b * 33 + c) * HH);
    const float4* pe = (const float4*)(P + 2 * CS + (long)(b * 33 + e) * HH);
    const float4* wv = (const float4*)(w2) + t * 3;

    float4 a = ps[t], bb = pc[t], cc = pe[t];
    float v0 = fmaxf(a.x + bb.x + cc.x, 0.f);
    float v1 = fmaxf(a.y + bb.y + cc.y, 0.f);
    float v2 = fmaxf(a.z + bb.z + cc.z, 0.f);
    float v3 = fmaxf(a.w + bb.w + cc.w, 0.f);
    float4 w0 = wv[0], w1 = wv[1], w2v = wv[2];
    // w layout: rows h -> [w(h,0), w(h,1), w(h,2)]
    float k0 = v0 * w0.x + v1 * w0.w + v2 * w1.z + v3 * w2v.y;
    float k1 = v0 * w0.y + v1 * w1.x + v2 * w1.w + v3 * w2v.z;
    float k2 = v0 * w0.z + v1 * w1.y + v2 * w2v.x + v3 * w2v.w;

#pragma unroll
    for (int off = 16; off; off >>= 1) {
        k0 += __shfl_xor_sync(0xFFFFFFFFu, k0, off);
        k1 += __shfl_xor_sync(0xFFFFFFFFu, k1, off);
        k2 += __shfl_xor_sync(0xFFFFFFFFu, k2, off);
    }
    __shared__ float red[3][6];
    const int lane = t & 31, w = t >> 5;
    if (lane == 0) { red[0][w] = k0; red[1][w] = k1; red[2][w] = k2; }
    __syncthreads();
    if (t == 0) {
        float r0 = b2[0], r1 = b2[1], r2 = b2[2];
#pragma unroll
        for (int i = 0; i < 6; i++) { r0 += red[0][i]; r1 += red[1][i]; r2 += red[2][i]; }
        long base = OUT_IOU_BASE + ((long)b * 3) * (32 * 33) + (long)s * 33 + e;
        out[base + 0 * 32 * 33] = r0;
        out[base + 1 * 32 * 33] = r1;
        out[base + 2 * 32 * 33] = r2;
    }
}

// ---------------------------------------------------------------------------
// Mask map
// ---------------------------------------------------------------------------
__global__ void mask_k(float* __restrict__ out)
{
    int idx = blockIdx.x * blockDim.x + threadIdx.x;
    if (idx >= 32 * 33) return;
    int i = idx / 33, j = idx % 33;
    float v = 0.f;
    int hi = (i + 17 < 33) ? (i + 17) : 33;
    if (j >= i + 1 && j < hi) v = 1.f;
    if (i < 16 && (i & 1) == 0 && j >= 18 + i && ((j - 18 - i) & 1) == 0) v = 1.f;
    out[OUT_MASK_BASE + idx] = v;
}

// ---------------------------------------------------------------------------
extern "C" void kernel_launch(void* const* d_in, const int* in_sizes, int n_in,
                              void* d_out, int out_size)
{
    const float* ht   = (const float*)d_in[0];
    const float* hc   = (const float*)d_in[1];
    const float* w_t1 = (const float*)d_in[2];
    const float* b_t1 = (const float*)d_in[3];
    const float* w_t2 = (const float*)d_in[4];
    const float* b_t2 = (const float*)d_in[5];
    const float* w_i1 = (const float*)d_in[6];
    const float* b_i1 = (const float*)d_in[7];
    const float* w_i2 = (const float*)d_in[8];
    const float* b_i2 = (const float*)d_in[9];
    float* out = (float*)d_out;

    float* proj; cudaGetSymbolAddress((void**)&proj, g_proj);
    __nv_bfloat16 *Athi, *Atlo, *Achi, *Aclo, *H1hi, *H1lo;
    __nv_bfloat16 *Bw1hi, *Bw1lo, *Bi1hi, *Bi1lo, *Bw2hi, *Bw2lo;
    cudaGetSymbolAddress((void**)&Athi, g_Athi);
    cudaGetSymbolAddress((void**)&Atlo, g_Atlo);
    cudaGetSymbolAddress((void**)&Achi, g_Achi);
    cudaGetSymbolAddress((void**)&Aclo, g_Aclo);
    cudaGetSymbolAddress((void**)&H1hi, g_H1hi);
    cudaGetSymbolAddress((void**)&H1lo, g_H1lo);
    cudaGetSymbolAddress((void**)&Bw1hi, g_Bw1hi);
    cudaGetSymbolAddress((void**)&Bw1lo, g_Bw1lo);
    cudaGetSymbolAddress((void**)&Bi1hi, g_Bi1hi);
    cudaGetSymbolAddress((void**)&Bi1lo, g_Bi1lo);
    cudaGetSymbolAddress((void**)&Bw2hi, g_Bw2hi);
    cudaGetSymbolAddress((void**)&Bw2lo, g_Bw2lo);

    cudaFuncSetAttribute(hgemm<0>, cudaFuncAttributeMaxDynamicSharedMemorySize, 98304);
    cudaFuncSetAttribute(hgemm<1>, cudaFuncAttributeMaxDynamicSharedMemorySize, 98304);
    cudaFuncSetAttribute(hgemm<2>, cudaFuncAttributeMaxDynamicSharedMemorySize, 98304);

    // --- preps ---
    split_k<<<(MTXT * DD + 255) / 256, 256>>>(ht, Athi, Atlo, (long)MTXT * DD);
    split_k<<<(MPROJ * DD + 255) / 256, 256>>>(hc, Achi, Aclo, (long)MPROJ * DD);
    tsplit_k<<<dim3(24, 24), dim3(32, 32)>>>(w_t1, Bw1hi, Bw1lo, DD, HH, 0, 0);
    tsplit_k<<<dim3(24, 24, 3), dim3(32, 32)>>>(w_i1, Bi1hi, Bi1lo, DD, HH,
                                                (long)DD * HH, (long)HH * DD);
    tsplit_k<<<dim3(NPAD / 32, 24), dim3(32, 32)>>>(w_t2, Bw2hi, Bw2lo, DD, VV, 0, 0);

    // --- GEMM1: h1 = relu(ht @ w_t1 + b_t1) -> bf16 hi/lo (fused) ---
    hgemm<1><<<dim3(HH / 128, MTXT / 128), 256, 98304>>>(
        Athi, Atlo, Bw1hi, Bw1lo, b_t1, nullptr, H1hi, H1lo,
        MTXT, HH, HH, 0, 0);

    // --- projections: proj[z] = hc @ w_i1_chunk[z] (+ b_i1 on z=0) ---
    hgemm<2><<<dim3(HH / 128, MPROJP / 128, 3), 256, 98304>>>(
        Achi, Aclo, Bi1hi, Bi1lo, b_i1, proj, nullptr, nullptr,
        MPROJ, HH, HH, (long)HH * DD, (long)MPROJP * HH);

    // --- vocab GEMM: logits_text = h1 @ w_t2 + b_t2 ---
    hgemm<0><<<dim3(NPAD / 128, MTXT / 128), 256, 98304>>>(
        H1hi, H1lo, Bw2hi, Bw2lo, b_t2, out, nullptr, nullptr,
        MTXT, VV, VV, 0, 0);

    // --- IoU combine + mask ---
    iou_combine_k<<<BB * TT * (TT + 1), 192>>>(proj, w_i2, b_i2, out);
    mask_k<<<(32 * 33 + 255) / 256, 256>>>(out);
}

// round 5
// speedup vs baseline: 3.6256x; 1.2273x over previous
#include <cuda_runtime.h>
#include <cuda_bf16.h>
#include <cuda_fp16.h>
#include <cstdint>

// Problem shapes
#define BB 32
#define LL 48
#define DD 768
#define TT 32
#define VV 30522
#define HH 768
#define NPAD 30592   // 239 * 128
#define MPROJ 1056   // 32*33
#define MPROJP 1152  // 9*128 padded
#define MTXT 1536

#define OUT_TEXT_ELEMS ((long)BB * LL * VV)
#define OUT_IOU_ELEMS  ((long)BB * 3 * TT * (TT+1))
#define OUT_IOU_BASE   (OUT_TEXT_ELEMS)
#define OUT_MASK_BASE  (OUT_TEXT_ELEMS + OUT_IOU_ELEMS)

// Scratch (device globals; no allocations allowed)
__device__ float g_proj[3L * MPROJP * HH];
__device__ __nv_bfloat16 g_Athi[(long)MTXT * DD],  g_Atlo[(long)MTXT * DD];   // ht split
__device__ __nv_bfloat16 g_Achi[(long)MPROJ * DD], g_Aclo[(long)MPROJ * DD];  // hc split
__device__ __half        g_H1hi[(long)MTXT * HH],  g_H1lo[(long)MTXT * HH];   // gemm1 out (fp16)
__device__ __nv_bfloat16 g_Bw1hi[(long)HH * DD],   g_Bw1lo[(long)HH * DD];    // w_t1^T
__device__ __nv_bfloat16 g_Bi1hi[3L * HH * DD],    g_Bi1lo[3L * HH * DD];     // w_i1^T chunks
__device__ __half        g_Bw2hi[(long)NPAD * DD];                            // w_t2^T (fp16 hi only)

// ---------------------------------------------------------------------------
// helpers
// ---------------------------------------------------------------------------
__device__ __forceinline__ uint32_t smem_u32(const void* p) {
    uint32_t a;
    asm("{ .reg .u64 t; cvta.to.shared.u64 t, %1; cvt.u32.u64 %0, t; }" : "=r"(a) : "l"(p));
    return a;
}
__device__ __forceinline__ void cp_async16(uint32_t saddr, const void* gptr) {
    asm volatile("cp.async.cg.shared.global [%0], [%1], 16;" :: "r"(saddr), "l"(gptr));
}
__device__ __forceinline__ void cp_async16z(uint32_t saddr, const void* gptr, bool pred) {
    int sz = pred ? 16 : 0;
    asm volatile("cp.async.cg.shared.global [%0], [%1], 16, %2;"
                 :: "r"(saddr), "l"(gptr), "r"(sz));
}
#define CP_COMMIT()  asm volatile("cp.async.commit_group;" ::: "memory")
#define CP_WAIT2()   asm volatile("cp.async.wait_group 2;" ::: "memory")
#define CP_WAIT1()   asm volatile("cp.async.wait_group 1;" ::: "memory")
#define CP_WAIT0()   asm volatile("cp.async.wait_group 0;" ::: "memory")

#define SWZ(o) ((o) ^ (((o) >> 3) & 0x70))

__device__ __forceinline__ void ldsm_x4(uint32_t addr, uint32_t& r0, uint32_t& r1,
                                        uint32_t& r2, uint32_t& r3) {
    asm volatile("ldmatrix.sync.aligned.m8n8.x4.shared.b16 {%0,%1,%2,%3}, [%4];"
                 : "=r"(r0), "=r"(r1), "=r"(r2), "=r"(r3) : "r"(addr));
}
__device__ __forceinline__ void mma_bf16(float* d, const uint32_t* a, const uint32_t* b) {
    asm volatile(
        "mma.sync.aligned.m16n8k16.row.col.f32.bf16.bf16.f32 "
        "{%0,%1,%2,%3}, {%4,%5,%6,%7}, {%8,%9}, {%0,%1,%2,%3};"
        : "+f"(d[0]), "+f"(d[1]), "+f"(d[2]), "+f"(d[3])
        : "r"(a[0]), "r"(a[1]), "r"(a[2]), "r"(a[3]), "r"(b[0]), "r"(b[1]));
}
__device__ __forceinline__ void mma_f16(float* d, const uint32_t* a, const uint32_t* b) {
    asm volatile(
        "mma.sync.aligned.m16n8k16.row.col.f32.f16.f16.f32 "
        "{%0,%1,%2,%3}, {%4,%5,%6,%7}, {%8,%9}, {%0,%1,%2,%3};"
        : "+f"(d[0]), "+f"(d[1]), "+f"(d[2]), "+f"(d[3])
        : "r"(a[0]), "r"(a[1]), "r"(a[2]), "r"(a[3]), "r"(b[0]), "r"(b[1]));
}

// ---------------------------------------------------------------------------
// bf16 HMMA 3-pass split GEMM (small GEMMs).  C = A*B^T (+bias); K=768.
// Tile 128x128, BK=64 (SW128), 3-stage cp.async pipeline, 256 thr.
// MODE 1: relu(acc+bias) -> fp16 hi/lo pair.  (text GEMM1)
// MODE 2: fp32 C, bias only when blockIdx.z==0. (projections)
// ---------------------------------------------------------------------------
#define NCHUNK 36  // 3 passes * 12 chunks of K=64

template<int MODE>
__global__ __launch_bounds__(256) void hgemm(
    const __nv_bfloat16* __restrict__ Ahi, const __nv_bfloat16* __restrict__ Alo,
    const __nv_bfloat16* __restrict__ Bhi, const __nv_bfloat16* __restrict__ Blo,
    const float* __restrict__ bias,
    float* __restrict__ Cf, __half* __restrict__ Chi, __half* __restrict__ Clo,
    int Mclip, long ldC, long zB, long zC)
{
    extern __shared__ char smem[];
    const uint32_t sbase = smem_u32(smem);
    const int tid  = threadIdx.x;
    const int wid  = tid >> 5;
    const int lane = tid & 31;
    const int row0 = blockIdx.y * 128;
    const int col0 = blockIdx.x * 128;
    const int wm = (wid & 1) * 64;
    const int wn = (wid >> 1) * 32;

    Bhi += (long)blockIdx.z * zB;
    Blo += (long)blockIdx.z * zB;
    if (MODE == 2) Cf += (long)blockIdx.z * zC;

    float acc[4][4][4];
#pragma unroll
    for (int i = 0; i < 4; i++)
#pragma unroll
        for (int j = 0; j < 4; j++)
#pragma unroll
            for (int r = 0; r < 4; r++) acc[i][j][r] = 0.f;

#define LOAD_CHUNK(KC)                                                          \
    {                                                                           \
        int pass = (KC) / 12;                                                   \
        int kk = ((KC) - pass * 12) * 64;                                       \
        const __nv_bfloat16* Ap = (pass == 1) ? Alo : Ahi;                      \
        const __nv_bfloat16* Bp = (pass == 2) ? Blo : Bhi;                      \
        uint32_t sA = sbase + ((KC) % 3) * 32768;                               \
        uint32_t sB = sA + 16384;                                               \
        _Pragma("unroll")                                                       \
        for (int i = 0; i < 4; i++) {                                           \
            int idx = tid + (i << 8);                                           \
            int m = idx >> 3, j = idx & 7;                                      \
            int grow = row0 + m;                                                \
            bool pa = grow < Mclip;                                             \
            cp_async16z(sA + SWZ(m * 128 + j * 16),                             \
                        Ap + (size_t)(pa ? grow : 0) * DD + kk + j * 8, pa);    \
            cp_async16(sB + SWZ(m * 128 + j * 16),                              \
                       Bp + (size_t)(col0 + m) * DD + kk + j * 8);              \
        }                                                                       \
        CP_COMMIT();                                                            \
    }

    LOAD_CHUNK(0);
    LOAD_CHUNK(1);
    LOAD_CHUNK(2);

    const int a_m  = lane & 15;
    const int a_kb = (lane >> 4) << 4;
    const int b_n  = (lane & 7) + ((lane >> 4) << 3);
    const int b_kb = ((lane >> 3) & 1) << 4;

    for (int kc = 0; kc < NCHUNK; kc++) {
        if (kc < NCHUNK - 2)       { CP_WAIT2(); }
        else if (kc == NCHUNK - 2) { CP_WAIT1(); }
        else                       { CP_WAIT0(); }
        __syncthreads();
        const uint32_t sA = sbase + (kc % 3) * 32768;
        const uint32_t sB = sA + 16384;

#pragma unroll
        for (int k16 = 0; k16 < 4; k16++) {
            const int kb = k16 * 32;
            uint32_t a[4][4], b[2][4];
#pragma unroll
            for (int mf = 0; mf < 4; mf++)
                ldsm_x4(sA + SWZ((wm + mf * 16 + a_m) * 128 + kb + a_kb),
                        a[mf][0], a[mf][1], a[mf][2], a[mf][3]);
#pragma unroll
            for (int np = 0; np < 2; np++)
                ldsm_x4(sB + SWZ((wn + np * 16 + b_n) * 128 + kb + b_kb),
                        b[np][0], b[np][1], b[np][2], b[np][3]);
#pragma unroll
            for (int mf = 0; mf < 4; mf++) {
#pragma unroll
                for (int nf = 0; nf < 4; nf++) {
                    uint32_t bb[2] = { b[nf >> 1][(nf & 1) * 2],
                                       b[nf >> 1][(nf & 1) * 2 + 1] };
                    mma_bf16(acc[mf][nf], a[mf], bb);
                }
            }
        }
        __syncthreads();
        if (kc + 3 < NCHUNK) LOAD_CHUNK(kc + 3);
    }
#undef LOAD_CHUNK

    const int em = lane >> 2;
    const int en = (lane & 3) * 2;
    const bool bias_on = (MODE != 2) || (blockIdx.z == 0);
#pragma unroll
    for (int mf = 0; mf < 4; mf++) {
#pragma unroll
        for (int half = 0; half < 2; half++) {
            int gr = row0 + wm + mf * 16 + em + half * 8;
#pragma unroll
            for (int nf = 0; nf < 4; nf++) {
                int gc = col0 + wn + nf * 8 + en;
                float vx = acc[mf][nf][half * 2];
                float vy = acc[mf][nf][half * 2 + 1];
                if (MODE == 1) {
                    vx = fmaxf(vx + __ldg(bias + gc), 0.f);
                    vy = fmaxf(vy + __ldg(bias + gc + 1), 0.f);
                    __half2 h, l;
                    h.x = __float2half_rn(vx);
                    h.y = __float2half_rn(vy);
                    l.x = __float2half_rn(vx - __half2float(h.x));
                    l.y = __float2half_rn(vy - __half2float(h.y));
                    *(__half2*)(Chi + (size_t)gr * ldC + gc) = h;
                    *(__half2*)(Clo + (size_t)gr * ldC + gc) = l;
                } else {  // MODE 2
                    if (bias_on) { vx += __ldg(bias + gc); vy += __ldg(bias + gc + 1); }
                    float2 v = { vx, vy };
                    *(float2*)(Cf + (size_t)gr * ldC + gc) = v;
                }
            }
        }
    }
}

// ---------------------------------------------------------------------------
// Vocab GEMM: fp16 2-term split. C = (Ahi+Alo) * Bhi^T + bias, fp32 out.
// Per chunk loads {Ahi, Alo, Bhi} (48KB), reuses B register fragments for
// both MMA groups. 12 chunks, double-buffered (96KB smem).
// grid = (NPAD/128, MTXT/128), 256 threads.
// ---------------------------------------------------------------------------
#define VCHUNK 12

__global__ __launch_bounds__(256) void hgemm_v(
    const __half* __restrict__ Ahi, const __half* __restrict__ Alo,
    const __half* __restrict__ Bhi, const float* __restrict__ bias,
    float* __restrict__ out)
{
    extern __shared__ char smem[];
    const uint32_t sbase = smem_u32(smem);
    const int tid  = threadIdx.x;
    const int wid  = tid >> 5;
    const int lane = tid & 31;
    const int row0 = blockIdx.y * 128;
    const int col0 = blockIdx.x * 128;
    const int wm = (wid & 1) * 64;
    const int wn = (wid >> 1) * 32;

    float acc[4][4][4];
#pragma unroll
    for (int i = 0; i < 4; i++)
#pragma unroll
        for (int j = 0; j < 4; j++)
#pragma unroll
            for (int r = 0; r < 4; r++) acc[i][j][r] = 0.f;

#define LOAD_CHUNKV(KC)                                                         \
    {                                                                           \
        int kk = (KC) * 64;                                                     \
        uint32_t st = sbase + ((KC) & 1) * 49152;                               \
        _Pragma("unroll")                                                       \
        for (int i = 0; i < 4; i++) {                                           \
            int idx = tid + (i << 8);                                           \
            int m = idx >> 3, j = idx & 7;                                      \
            uint32_t so = SWZ(m * 128 + j * 16);                                \
            size_t ga = (size_t)(row0 + m) * DD + kk + j * 8;                   \
            cp_async16(st + so,         Ahi + ga);                              \
            cp_async16(st + 16384 + so, Alo + ga);                              \
            cp_async16(st + 32768 + so,                                         \
                       Bhi + (size_t)(col0 + m) * DD + kk + j * 8);             \
        }                                                                       \
        CP_COMMIT();                                                            \
    }

    LOAD_CHUNKV(0);
    LOAD_CHUNKV(1);

    const int a_m  = lane & 15;
    const int a_kb = (lane >> 4) << 4;
    const int b_n  = (lane & 7) + ((lane >> 4) << 3);
    const int b_kb = ((lane >> 3) & 1) << 4;

    for (int kc = 0; kc < VCHUNK; kc++) {
        if (kc < VCHUNK - 1) { CP_WAIT1(); } else { CP_WAIT0(); }
        __syncthreads();
        const uint32_t st = sbase + (kc & 1) * 49152;

#pragma unroll
        for (int k16 = 0; k16 < 4; k16++) {
            const int kb = k16 * 32;
            uint32_t a[4][4], b[2][4];
#pragma unroll
            for (int np = 0; np < 2; np++)
                ldsm_x4(st + 32768 + SWZ((wn + np * 16 + b_n) * 128 + kb + b_kb),
                        b[np][0], b[np][1], b[np][2], b[np][3]);
            // hi pass
#pragma unroll
            for (int mf = 0; mf < 4; mf++)
                ldsm_x4(st + SWZ((wm + mf * 16 + a_m) * 128 + kb + a_kb),
                        a[mf][0], a[mf][1], a[mf][2], a[mf][3]);
#pragma unroll
            for (int mf = 0; mf < 4; mf++) {
#pragma unroll
                for (int nf = 0; nf < 4; nf++) {
                    uint32_t bb[2] = { b[nf >> 1][(nf & 1) * 2],
                                       b[nf >> 1][(nf & 1) * 2 + 1] };
                    mma_f16(acc[mf][nf], a[mf], bb);
                }
            }
            // lo pass (reuse a regs, b regs)
#pragma unroll
            for (int mf = 0; mf < 4; mf++)
                ldsm_x4(st + 16384 + SWZ((wm + mf * 16 + a_m) * 128 + kb + a_kb),
                        a[mf][0], a[mf][1], a[mf][2], a[mf][3]);
#pragma unroll
            for (int mf = 0; mf < 4; mf++) {
#pragma unroll
                for (int nf = 0; nf < 4; nf++) {
                    uint32_t bb[2] = { b[nf >> 1][(nf & 1) * 2],
                                       b[nf >> 1][(nf & 1) * 2 + 1] };
                    mma_f16(acc[mf][nf], a[mf], bb);
                }
            }
        }
        __syncthreads();
        if (kc + 2 < VCHUNK) LOAD_CHUNKV(kc + 2);
    }
#undef LOAD_CHUNKV

    const int em = lane >> 2;
    const int en = (lane & 3) * 2;
#pragma unroll
    for (int mf = 0; mf < 4; mf++) {
#pragma unroll
        for (int half = 0; half < 2; half++) {
            int gr = row0 + wm + mf * 16 + em + half * 8;
            float* orow = out + (size_t)gr * VV;
#pragma unroll
            for (int nf = 0; nf < 4; nf++) {
                int gc = col0 + wn + nf * 8 + en;
                if (gc + 1 < VV) {
                    float2 v = { acc[mf][nf][half * 2]     + __ldg(bias + gc),
                                 acc[mf][nf][half * 2 + 1] + __ldg(bias + gc + 1) };
                    *(float2*)(orow + gc) = v;
                } else if (gc < VV) {
                    orow[gc] = acc[mf][nf][half * 2] + __ldg(bias + gc);
                }
            }
        }
    }
}

// ---------------------------------------------------------------------------
// fp32 -> bf16 hi/lo split (elementwise)
// ---------------------------------------------------------------------------
__global__ void split_k(const float* __restrict__ in, __nv_bfloat16* __restrict__ hi,
                        __nv_bfloat16* __restrict__ lo, long n)
{
    long i = (long)blockIdx.x * blockDim.x + threadIdx.x;
    if (i >= n) return;
    float x = in[i];
    __nv_bfloat16 h = __float2bfloat16(x);
    hi[i] = h;
    lo[i] = __float2bfloat16(x - __bfloat162float(h));
}

// ---------------------------------------------------------------------------
// transpose + split (bf16 hi/lo), z-batched
// ---------------------------------------------------------------------------
__global__ void tsplit_k(const float* __restrict__ in, __nv_bfloat16* __restrict__ hi,
                         __nv_bfloat16* __restrict__ lo, int K, int N,
                         long inZ, long outZ)
{
    in += (long)blockIdx.z * inZ;
    hi += (long)blockIdx.z * outZ;
    lo += (long)blockIdx.z * outZ;
    __shared__ float t[32][33];
    int n0 = blockIdx.x * 32, k0 = blockIdx.y * 32;
    int n = n0 + threadIdx.x, k = k0 + threadIdx.y;
    t[threadIdx.y][threadIdx.x] = (n < N) ? in[(long)k * N + n] : 0.f;
    __syncthreads();
    int orow = n0 + threadIdx.y, ocol = k0 + threadIdx.x;
    float x = t[threadIdx.x][threadIdx.y];
    __nv_bfloat16 h = __float2bfloat16(x);
    hi[(long)orow * K + ocol] = h;
    lo[(long)orow * K + ocol] = __float2bfloat16(x - __bfloat162float(h));
}

// ---------------------------------------------------------------------------
// transpose, fp16 hi only (w_t2)
// ---------------------------------------------------------------------------
__global__ void tsplit_h(const float* __restrict__ in, __half* __restrict__ hi,
                         int K, int N)
{
    __shared__ float t[32][33];
    int n0 = blockIdx.x * 32, k0 = blockIdx.y * 32;
    int n = n0 + threadIdx.x, k = k0 + threadIdx.y;
    t[threadIdx.y][threadIdx.x] = (n < N) ? in[(long)k * N + n] : 0.f;
    __syncthreads();
    int orow = n0 + threadIdx.y, ocol = k0 + threadIdx.x;
    hi[(long)orow * K + ocol] = __float2half_rn(t[threadIdx.x][threadIdx.y]);
}

// ---------------------------------------------------------------------------
// IoU combine: b_i1 already folded into chunk-0 projection.
// ---------------------------------------------------------------------------
__global__ __launch_bounds__(192) void iou_combine_k(
    const float* __restrict__ P, const float* __restrict__ w2,
    const float* __restrict__ b2, float* __restrict__ out)
{
    const int idx = blockIdx.x;
    const int e = idx % 33;
    const int s = (idx / 33) % 32;
    const int b = idx / (33 * 32);
    const int c = (s + e) >> 1;

    const long CS = (long)MPROJP * HH;
    const int t = threadIdx.x;
    const float4* ps = (const float4*)(P + (long)(b * 33 + s) * HH);
    const float4* pc = (const float4*)(P + CS + (long)(b * 33 + c) * HH);
    const float4* pe = (const float4*)(P + 2 * CS + (long)(b * 33 + e) * HH);
    const float4* wv = (const float4*)(w2) + t * 3;

    float4 a = ps[t], bb = pc[t], cc = pe[t];
    float v0 = fmaxf(a.x + bb.x + cc.x, 0.f);
    float v1 = fmaxf(a.y + bb.y + cc.y, 0.f);
    float v2 = fmaxf(a.z + bb.z + cc.z, 0.f);
    float v3 = fmaxf(a.w + bb.w + cc.w, 0.f);
    float4 w0 = wv[0], w1 = wv[1], w2v = wv[2];
    float k0 = v0 * w0.x + v1 * w0.w + v2 * w1.z + v3 * w2v.y;
    float k1 = v0 * w0.y + v1 * w1.x + v2 * w1.w + v3 * w2v.z;
    float k2 = v0 * w0.z + v1 * w1.y + v2 * w2v.x + v3 * w2v.w;

#pragma unroll
    for (int off = 16; off; off >>= 1) {
        k0 += __shfl_xor_sync(0xFFFFFFFFu, k0, off);
        k1 += __shfl_xor_sync(0xFFFFFFFFu, k1, off);
        k2 += __shfl_xor_sync(0xFFFFFFFFu, k2, off);
    }
    __shared__ float red[3][6];
    const int lane = t & 31, w = t >> 5;
    if (lane == 0) { red[0][w] = k0; red[1][w] = k1; red[2][w] = k2; }
    __syncthreads();
    if (t == 0) {
        float r0 = b2[0], r1 = b2[1], r2 = b2[2];
#pragma unroll
        for (int i = 0; i < 6; i++) { r0 += red[0][i]; r1 += red[1][i]; r2 += red[2][i]; }
        long base = OUT_IOU_BASE + ((long)b * 3) * (32 * 33) + (long)s * 33 + e;
        out[base + 0 * 32 * 33] = r0;
        out[base + 1 * 32 * 33] = r1;
        out[base + 2 * 32 * 33] = r2;
    }
}

// ---------------------------------------------------------------------------
// Mask map
// ---------------------------------------------------------------------------
__global__ void mask_k(float* __restrict__ out)
{
    int idx = blockIdx.x * blockDim.x + threadIdx.x;
    if (idx >= 32 * 33) return;
    int i = idx / 33, j = idx % 33;
    float v = 0.f;
    int hi = (i + 17 < 33) ? (i + 17) : 33;
    if (j >= i + 1 && j < hi) v = 1.f;
    if (i < 16 && (i & 1) == 0 && j >= 18 + i && ((j - 18 - i) & 1) == 0) v = 1.f;
    out[OUT_MASK_BASE + idx] = v;
}

// ---------------------------------------------------------------------------
extern "C" void kernel_launch(void* const* d_in, const int* in_sizes, int n_in,
                              void* d_out, int out_size)
{
    const float* ht   = (const float*)d_in[0];
    const float* hc   = (const float*)d_in[1];
    const float* w_t1 = (const float*)d_in[2];
    const float* b_t1 = (const float*)d_in[3];
    const float* w_t2 = (const float*)d_in[4];
    const float* b_t2 = (const float*)d_in[5];
    const float* w_i1 = (const float*)d_in[6];
    const float* b_i1 = (const float*)d_in[7];
    const float* w_i2 = (const float*)d_in[8];
    const float* b_i2 = (const float*)d_in[9];
    float* out = (float*)d_out;

    float* proj; cudaGetSymbolAddress((void**)&proj, g_proj);
    __nv_bfloat16 *Athi, *Atlo, *Achi, *Aclo;
    __nv_bfloat16 *Bw1hi, *Bw1lo, *Bi1hi, *Bi1lo;
    __half *H1hi, *H1lo, *Bw2hi;
    cudaGetSymbolAddress((void**)&Athi, g_Athi);
    cudaGetSymbolAddress((void**)&Atlo, g_Atlo);
    cudaGetSymbolAddress((void**)&Achi, g_Achi);
    cudaGetSymbolAddress((void**)&Aclo, g_Aclo);
    cudaGetSymbolAddress((void**)&H1hi, g_H1hi);
    cudaGetSymbolAddress((void**)&H1lo, g_H1lo);
    cudaGetSymbolAddress((void**)&Bw1hi, g_Bw1hi);
    cudaGetSymbolAddress((void**)&Bw1lo, g_Bw1lo);
    cudaGetSymbolAddress((void**)&Bi1hi, g_Bi1hi);
    cudaGetSymbolAddress((void**)&Bi1lo, g_Bi1lo);
    cudaGetSymbolAddress((void**)&Bw2hi, g_Bw2hi);

    cudaFuncSetAttribute(hgemm<1>, cudaFuncAttributeMaxDynamicSharedMemorySize, 98304);
    cudaFuncSetAttribute(hgemm<2>, cudaFuncAttributeMaxDynamicSharedMemorySize, 98304);
    cudaFuncSetAttribute(hgemm_v,  cudaFuncAttributeMaxDynamicSharedMemorySize, 98304);

    // --- preps ---
    split_k<<<(MTXT * DD + 255) / 256, 256>>>(ht, Athi, Atlo, (long)MTXT * DD);
    split_k<<<(MPROJ * DD + 255) / 256, 256>>>(hc, Achi, Aclo, (long)MPROJ * DD);
    tsplit_k<<<dim3(24, 24), dim3(32, 32)>>>(w_t1, Bw1hi, Bw1lo, DD, HH, 0, 0);
    tsplit_k<<<dim3(24, 24, 3), dim3(32, 32)>>>(w_i1, Bi1hi, Bi1lo, DD, HH,
                                                (long)DD * HH, (long)HH * DD);
    tsplit_h<<<dim3(NPAD / 32, 24), dim3(32, 32)>>>(w_t2, Bw2hi, DD, VV);

    // --- GEMM1: h1 = relu(ht @ w_t1 + b_t1) -> fp16 hi/lo (fused) ---
    hgemm<1><<<dim3(HH / 128, MTXT / 128), 256, 98304>>>(
        Athi, Atlo, Bw1hi, Bw1lo, b_t1, nullptr, H1hi, H1lo,
        MTXT, HH, 0, 0);

    // --- projections: proj[z] = hc @ w_i1_chunk[z] (+ b_i1 on z=0) ---
    hgemm<2><<<dim3(HH / 128, MPROJP / 128, 3), 256, 98304>>>(
        Achi, Aclo, Bi1hi, Bi1lo, b_i1, proj, nullptr, nullptr,
        MPROJ, HH, (long)HH * DD, (long)MPROJP * HH);

    // --- vocab GEMM: logits_text = h1 @ w_t2 + b_t2 (fp16 2-term) ---
    hgemm_v<<<dim3(NPAD / 128, MTXT / 128), 256, 98304>>>(
        H1hi, H1lo, Bw2hi, b_t2, out);

    // --- IoU combine + mask ---
    iou_combine_k<<<BB * TT * (TT + 1), 192>>>(proj, w_i2, b_i2, out);
    mask_k<<<(32 * 33 + 255) / 256, 256>>>(out);
}

// round 6
// speedup vs baseline: 4.2306x; 1.1669x over previous
#include <cuda_runtime.h>
#include <cuda_bf16.h>
#include <cuda_fp16.h>
#include <cstdint>

// Problem shapes
#define BB 32
#define LL 48
#define DD 768
#define TT 32
#define VV 30522
#define HH 768
#define NPAD 30592   // 239 * 128
#define MPROJ 1056   // 32*33
#define MPROJP 1152  // 9*128 padded
#define MTXT 1536

#define OUT_TEXT_ELEMS ((long)BB * LL * VV)
#define OUT_IOU_ELEMS  ((long)BB * 3 * TT * (TT+1))
#define OUT_IOU_BASE   (OUT_TEXT_ELEMS)
#define OUT_MASK_BASE  (OUT_TEXT_ELEMS + OUT_IOU_ELEMS)

#define PGRID 162   // 6 * 9 * 3 projection tiles
#define VGRID 2868  // 239 * 12 vocab tiles

// Scratch (device globals; no allocations allowed)
__device__ float g_proj[3L * MPROJP * HH];
__device__ __nv_bfloat16 g_Athi[(long)MTXT * DD],  g_Atlo[(long)MTXT * DD];
__device__ __nv_bfloat16 g_Achi[(long)MPROJ * DD], g_Aclo[(long)MPROJ * DD];
__device__ __half        g_H1hi[(long)MTXT * HH],  g_H1lo[(long)MTXT * HH];
__device__ __nv_bfloat16 g_Bw1hi[(long)HH * DD],   g_Bw1lo[(long)HH * DD];
__device__ __nv_bfloat16 g_Bi1hi[3L * HH * DD],    g_Bi1lo[3L * HH * DD];
__device__ __half        g_Bw2hi[(long)NPAD * DD];

// ---------------------------------------------------------------------------
// helpers
// ---------------------------------------------------------------------------
__device__ __forceinline__ uint32_t smem_u32(const void* p) {
    uint32_t a;
    asm("{ .reg .u64 t; cvta.to.shared.u64 t, %1; cvt.u32.u64 %0, t; }" : "=r"(a) : "l"(p));
    return a;
}
__device__ __forceinline__ void cp_async16(uint32_t saddr, const void* gptr) {
    asm volatile("cp.async.cg.shared.global [%0], [%1], 16;" :: "r"(saddr), "l"(gptr));
}
__device__ __forceinline__ void cp_async16z(uint32_t saddr, const void* gptr, bool pred) {
    int sz = pred ? 16 : 0;
    asm volatile("cp.async.cg.shared.global [%0], [%1], 16, %2;"
                 :: "r"(saddr), "l"(gptr), "r"(sz));
}
#define CP_COMMIT()  asm volatile("cp.async.commit_group;" ::: "memory")
#define CP_WAIT2()   asm volatile("cp.async.wait_group 2;" ::: "memory")
#define CP_WAIT1()   asm volatile("cp.async.wait_group 1;" ::: "memory")
#define CP_WAIT0()   asm volatile("cp.async.wait_group 0;" ::: "memory")

#define SWZ(o) ((o) ^ (((o) >> 3) & 0x70))

__device__ __forceinline__ void ldsm_x4(uint32_t addr, uint32_t& r0, uint32_t& r1,
                                        uint32_t& r2, uint32_t& r3) {
    asm volatile("ldmatrix.sync.aligned.m8n8.x4.shared.b16 {%0,%1,%2,%3}, [%4];"
                 : "=r"(r0), "=r"(r1), "=r"(r2), "=r"(r3) : "r"(addr));
}
__device__ __forceinline__ void mma_bf16(float* d, const uint32_t* a, const uint32_t* b) {
    asm volatile(
        "mma.sync.aligned.m16n8k16.row.col.f32.bf16.bf16.f32 "
        "{%0,%1,%2,%3}, {%4,%5,%6,%7}, {%8,%9}, {%0,%1,%2,%3};"
        : "+f"(d[0]), "+f"(d[1]), "+f"(d[2]), "+f"(d[3])
        : "r"(a[0]), "r"(a[1]), "r"(a[2]), "r"(a[3]), "r"(b[0]), "r"(b[1]));
}
__device__ __forceinline__ void mma_f16(float* d, const uint32_t* a, const uint32_t* b) {
    asm volatile(
        "mma.sync.aligned.m16n8k16.row.col.f32.f16.f16.f32 "
        "{%0,%1,%2,%3}, {%4,%5,%6,%7}, {%8,%9}, {%0,%1,%2,%3};"
        : "+f"(d[0]), "+f"(d[1]), "+f"(d[2]), "+f"(d[3])
        : "r"(a[0]), "r"(a[1]), "r"(a[2]), "r"(a[3]), "r"(b[0]), "r"(b[1]));
}

// ---------------------------------------------------------------------------
// GEMM1: bf16 3-pass split, relu(acc+bias) -> fp16 hi/lo. K=768, tile 128x128.
// ---------------------------------------------------------------------------
#define NCHUNK 36

__global__ __launch_bounds__(256, 2) void hgemm1(
    const __nv_bfloat16* __restrict__ Ahi, const __nv_bfloat16* __restrict__ Alo,
    const __nv_bfloat16* __restrict__ Bhi, const __nv_bfloat16* __restrict__ Blo,
    const float* __restrict__ bias,
    __half* __restrict__ Chi, __half* __restrict__ Clo)
{
    extern __shared__ char smem[];
    const uint32_t sbase = smem_u32(smem);
    const int tid  = threadIdx.x;
    const int wid  = tid >> 5;
    const int lane = tid & 31;
    const int row0 = blockIdx.y * 128;
    const int col0 = blockIdx.x * 128;
    const int wm = (wid & 1) * 64;
    const int wn = (wid >> 1) * 32;

    float acc[4][4][4];
#pragma unroll
    for (int i = 0; i < 4; i++)
#pragma unroll
        for (int j = 0; j < 4; j++)
#pragma unroll
            for (int r = 0; r < 4; r++) acc[i][j][r] = 0.f;

#define LOAD_CHUNK1(KC)                                                         \
    {                                                                           \
        int pass = (KC) / 12;                                                   \
        int kk = ((KC) - pass * 12) * 64;                                       \
        const __nv_bfloat16* Ap = (pass == 1) ? Alo : Ahi;                      \
        const __nv_bfloat16* Bp = (pass == 2) ? Blo : Bhi;                      \
        uint32_t sA = sbase + ((KC) % 3) * 32768;                               \
        uint32_t sB = sA + 16384;                                               \
        _Pragma("unroll")                                                       \
        for (int i = 0; i < 4; i++) {                                           \
            int idx = tid + (i << 8);                                           \
            int m = idx >> 3, j = idx & 7;                                      \
            cp_async16(sA + SWZ(m * 128 + j * 16),                              \
                       Ap + (size_t)(row0 + m) * DD + kk + j * 8);              \
            cp_async16(sB + SWZ(m * 128 + j * 16),                              \
                       Bp + (size_t)(col0 + m) * DD + kk + j * 8);              \
        }                                                                       \
        CP_COMMIT();                                                            \
    }

    LOAD_CHUNK1(0);
    LOAD_CHUNK1(1);
    LOAD_CHUNK1(2);

    const int a_m  = lane & 15;
    const int a_kb = (lane >> 4) << 4;
    const int b_n  = (lane & 7) + ((lane >> 4) << 3);
    const int b_kb = ((lane >> 3) & 1) << 4;

    for (int kc = 0; kc < NCHUNK; kc++) {
        if (kc < NCHUNK - 2)       { CP_WAIT2(); }
        else if (kc == NCHUNK - 2) { CP_WAIT1(); }
        else                       { CP_WAIT0(); }
        __syncthreads();
        const uint32_t sA = sbase + (kc % 3) * 32768;
        const uint32_t sB = sA + 16384;

#pragma unroll
        for (int k16 = 0; k16 < 4; k16++) {
            const int kb = k16 * 32;
            uint32_t a[4][4], b[2][4];
#pragma unroll
            for (int mf = 0; mf < 4; mf++)
                ldsm_x4(sA + SWZ((wm + mf * 16 + a_m) * 128 + kb + a_kb),
                        a[mf][0], a[mf][1], a[mf][2], a[mf][3]);
#pragma unroll
            for (int np = 0; np < 2; np++)
                ldsm_x4(sB + SWZ((wn + np * 16 + b_n) * 128 + kb + b_kb),
                        b[np][0], b[np][1], b[np][2], b[np][3]);
#pragma unroll
            for (int mf = 0; mf < 4; mf++) {
#pragma unroll
                for (int nf = 0; nf < 4; nf++) {
                    uint32_t bb[2] = { b[nf >> 1][(nf & 1) * 2],
                                       b[nf >> 1][(nf & 1) * 2 + 1] };
                    mma_bf16(acc[mf][nf], a[mf], bb);
                }
            }
        }
        __syncthreads();
        if (kc + 3 < NCHUNK) LOAD_CHUNK1(kc + 3);
    }
#undef LOAD_CHUNK1

    const int em = lane >> 2;
    const int en = (lane & 3) * 2;
#pragma unroll
    for (int mf = 0; mf < 4; mf++) {
#pragma unroll
        for (int half = 0; half < 2; half++) {
            int gr = row0 + wm + mf * 16 + em + half * 8;
#pragma unroll
            for (int nf = 0; nf < 4; nf++) {
                int gc = col0 + wn + nf * 8 + en;
                float vx = fmaxf(acc[mf][nf][half * 2]     + __ldg(bias + gc), 0.f);
                float vy = fmaxf(acc[mf][nf][half * 2 + 1] + __ldg(bias + gc + 1), 0.f);
                __half2 h, l;
                h.x = __float2half_rn(vx);
                h.y = __float2half_rn(vy);
                l.x = __float2half_rn(vx - __half2float(h.x));
                l.y = __float2half_rn(vy - __half2float(h.y));
                *(__half2*)(Chi + (size_t)gr * HH + gc) = h;
                *(__half2*)(Clo + (size_t)gr * HH + gc) = l;
            }
        }
    }
}

// ---------------------------------------------------------------------------
// Fat kernel: blocks [0, PGRID) do projection tiles (bf16 3-pass),
// blocks [PGRID, PGRID+VGRID) do vocab tiles (fp16 2-term).
// ---------------------------------------------------------------------------
__global__ __launch_bounds__(256, 2) void fat_gemm(
    const __half* __restrict__ VAhi, const __half* __restrict__ VAlo,
    const __half* __restrict__ VBhi, const float* __restrict__ vbias,
    float* __restrict__ out,
    const __nv_bfloat16* __restrict__ PAhi, const __nv_bfloat16* __restrict__ PAlo,
    const __nv_bfloat16* __restrict__ PBhi, const __nv_bfloat16* __restrict__ PBlo,
    const float* __restrict__ pbias, float* __restrict__ proj)
{
    extern __shared__ char smem[];
    const uint32_t sbase = smem_u32(smem);
    const int tid  = threadIdx.x;
    const int wid  = tid >> 5;
    const int lane = tid & 31;
    const int wm = (wid & 1) * 64;
    const int wn = (wid >> 1) * 32;

    const int a_m  = lane & 15;
    const int a_kb = (lane >> 4) << 4;
    const int b_n  = (lane & 7) + ((lane >> 4) << 3);
    const int b_kb = ((lane >> 3) & 1) << 4;
    const int em = lane >> 2;
    const int en = (lane & 3) * 2;

    float acc[4][4][4];
#pragma unroll
    for (int i = 0; i < 4; i++)
#pragma unroll
        for (int j = 0; j < 4; j++)
#pragma unroll
            for (int r = 0; r < 4; r++) acc[i][j][r] = 0.f;

    if (blockIdx.x < PGRID) {
        // ----------------- projection path (bf16 3-pass) -----------------
        const int p  = blockIdx.x;
        const int col0 = (p % 6) * 128;
        const int row0 = ((p / 6) % 9) * 128;
        const int pz = p / 54;
        const __nv_bfloat16* Bhi = PBhi + (long)pz * HH * DD;
        const __nv_bfloat16* Blo = PBlo + (long)pz * HH * DD;
        float* Cf = proj + (long)pz * MPROJP * HH;

#define LOAD_CHUNKP(KC)                                                         \
    {                                                                           \
        int pass = (KC) / 12;                                                   \
        int kk = ((KC) - pass * 12) * 64;                                       \
        const __nv_bfloat16* Ap = (pass == 1) ? PAlo : PAhi;                    \
        const __nv_bfloat16* Bp = (pass == 2) ? Blo : Bhi;                      \
        uint32_t sA = sbase + ((KC) % 3) * 32768;                               \
        uint32_t sB = sA + 16384;                                               \
        _Pragma("unroll")                                                       \
        for (int i = 0; i < 4; i++) {                                           \
            int idx = tid + (i << 8);                                           \
            int m = idx >> 3, j = idx & 7;                                      \
            int grow = row0 + m;                                                \
            bool pa = grow < MPROJ;                                             \
            cp_async16z(sA + SWZ(m * 128 + j * 16),                             \
                        Ap + (size_t)(pa ? grow : 0) * DD + kk + j * 8, pa);    \
            cp_async16(sB + SWZ(m * 128 + j * 16),                              \
                       Bp + (size_t)(col0 + m) * DD + kk + j * 8);              \
        }                                                                       \
        CP_COMMIT();                                                            \
    }

        LOAD_CHUNKP(0);
        LOAD_CHUNKP(1);
        LOAD_CHUNKP(2);

        for (int kc = 0; kc < NCHUNK; kc++) {
            if (kc < NCHUNK - 2)       { CP_WAIT2(); }
            else if (kc == NCHUNK - 2) { CP_WAIT1(); }
            else                       { CP_WAIT0(); }
            __syncthreads();
            const uint32_t sA = sbase + (kc % 3) * 32768;
            const uint32_t sB = sA + 16384;

#pragma unroll
            for (int k16 = 0; k16 < 4; k16++) {
                const int kb = k16 * 32;
                uint32_t a[4][4], b[2][4];
#pragma unroll
                for (int mf = 0; mf < 4; mf++)
                    ldsm_x4(sA + SWZ((wm + mf * 16 + a_m) * 128 + kb + a_kb),
                            a[mf][0], a[mf][1], a[mf][2], a[mf][3]);
#pragma unroll
                for (int np = 0; np < 2; np++)
                    ldsm_x4(sB + SWZ((wn + np * 16 + b_n) * 128 + kb + b_kb),
                            b[np][0], b[np][1], b[np][2], b[np][3]);
#pragma unroll
                for (int mf = 0; mf < 4; mf++) {
#pragma unroll
                    for (int nf = 0; nf < 4; nf++) {
                        uint32_t bb[2] = { b[nf >> 1][(nf & 1) * 2],
                                           b[nf >> 1][(nf & 1) * 2 + 1] };
                        mma_bf16(acc[mf][nf], a[mf], bb);
                    }
                }
            }
            __syncthreads();
            if (kc + 3 < NCHUNK) LOAD_CHUNKP(kc + 3);
        }
#undef LOAD_CHUNKP

        const bool bias_on = (pz == 0);
#pragma unroll
        for (int mf = 0; mf < 4; mf++) {
#pragma unroll
            for (int half = 0; half < 2; half++) {
                int gr = row0 + wm + mf * 16 + em + half * 8;
#pragma unroll
                for (int nf = 0; nf < 4; nf++) {
                    int gc = col0 + wn + nf * 8 + en;
                    float vx = acc[mf][nf][half * 2];
                    float vy = acc[mf][nf][half * 2 + 1];
                    if (bias_on) { vx += __ldg(pbias + gc); vy += __ldg(pbias + gc + 1); }
                    float2 v = { vx, vy };
                    *(float2*)(Cf + (size_t)gr * HH + gc) = v;
                }
            }
        }
    } else {
        // ----------------- vocab path (fp16 2-term) -----------------
        const int v = blockIdx.x - PGRID;
        const int col0 = (v % 239) * 128;
        const int row0 = (v / 239) * 128;

#define VCHUNK 12
#define LOAD_CHUNKV(KC)                                                         \
    {                                                                           \
        int kk = (KC) * 64;                                                     \
        uint32_t st = sbase + ((KC) & 1) * 49152;                               \
        _Pragma("unroll")                                                       \
        for (int i = 0; i < 4; i++) {                                           \
            int idx = tid + (i << 8);                                           \
            int m = idx >> 3, j = idx & 7;                                      \
            uint32_t so = SWZ(m * 128 + j * 16);                                \
            size_t ga = (size_t)(row0 + m) * DD + kk + j * 8;                   \
            cp_async16(st + so,         VAhi + ga);                             \
            cp_async16(st + 16384 + so, VAlo + ga);                             \
            cp_async16(st + 32768 + so,                                         \
                       VBhi + (size_t)(col0 + m) * DD + kk + j * 8);            \
        }                                                                       \
        CP_COMMIT();                                                            \
    }

        LOAD_CHUNKV(0);
        LOAD_CHUNKV(1);

        for (int kc = 0; kc < VCHUNK; kc++) {
            if (kc < VCHUNK - 1) { CP_WAIT1(); } else { CP_WAIT0(); }
            __syncthreads();
            const uint32_t st = sbase + (kc & 1) * 49152;

#pragma unroll
            for (int k16 = 0; k16 < 4; k16++) {
                const int kb = k16 * 32;
                uint32_t a[4][4], b[2][4];
#pragma unroll
                for (int np = 0; np < 2; np++)
                    ldsm_x4(st + 32768 + SWZ((wn + np * 16 + b_n) * 128 + kb + b_kb),
                            b[np][0], b[np][1], b[np][2], b[np][3]);
#pragma unroll
                for (int mf = 0; mf < 4; mf++)
                    ldsm_x4(st + SWZ((wm + mf * 16 + a_m) * 128 + kb + a_kb),
                            a[mf][0], a[mf][1], a[mf][2], a[mf][3]);
#pragma unroll
                for (int mf = 0; mf < 4; mf++) {
#pragma unroll
                    for (int nf = 0; nf < 4; nf++) {
                        uint32_t bb[2] = { b[nf >> 1][(nf & 1) * 2],
                                           b[nf >> 1][(nf & 1) * 2 + 1] };
                        mma_f16(acc[mf][nf], a[mf], bb);
                    }
                }
#pragma unroll
                for (int mf = 0; mf < 4; mf++)
                    ldsm_x4(st + 16384 + SWZ((wm + mf * 16 + a_m) * 128 + kb + a_kb),
                            a[mf][0], a[mf][1], a[mf][2], a[mf][3]);
#pragma unroll
                for (int mf = 0; mf < 4; mf++) {
#pragma unroll
                    for (int nf = 0; nf < 4; nf++) {
                        uint32_t bb[2] = { b[nf >> 1][(nf & 1) * 2],
                                           b[nf >> 1][(nf & 1) * 2 + 1] };
                        mma_f16(acc[mf][nf], a[mf], bb);
                    }
                }
            }
            __syncthreads();
            if (kc + 2 < VCHUNK) LOAD_CHUNKV(kc + 2);
        }
#undef LOAD_CHUNKV

#pragma unroll
        for (int mf = 0; mf < 4; mf++) {
#pragma unroll
            for (int half = 0; half < 2; half++) {
                int gr = row0 + wm + mf * 16 + em + half * 8;
                float* orow = out + (size_t)gr * VV;
#pragma unroll
                for (int nf = 0; nf < 4; nf++) {
                    int gc = col0 + wn + nf * 8 + en;
                    if (gc + 1 < VV) {
                        float2 v = { acc[mf][nf][half * 2]     + __ldg(vbias + gc),
                                     acc[mf][nf][half * 2 + 1] + __ldg(vbias + gc + 1) };
                        *(float2*)(orow + gc) = v;
                    } else if (gc < VV) {
                        orow[gc] = acc[mf][nf][half * 2] + __ldg(vbias + gc);
                    }
                }
            }
        }
    }
}

// ---------------------------------------------------------------------------
// fp32 -> bf16 hi/lo split over two tensors (ht then hc)
// ---------------------------------------------------------------------------
__global__ void split_both_k(
    const float* __restrict__ in1, __nv_bfloat16* __restrict__ hi1, __nv_bfloat16* __restrict__ lo1, long n1,
    const float* __restrict__ in2, __nv_bfloat16* __restrict__ hi2, __nv_bfloat16* __restrict__ lo2, long n2)
{
    long i = (long)blockIdx.x * blockDim.x + threadIdx.x;
    const float* in; __nv_bfloat16 *hi, *lo;
    if (i < n1) { in = in1; hi = hi1; lo = lo1; }
    else if (i < n1 + n2) { i -= n1; in = in2; hi = hi2; lo = lo2; }
    else return;
    float x = in[i];
    __nv_bfloat16 h = __float2bfloat16(x);
    hi[i] = h;
    lo[i] = __float2bfloat16(x - __bfloat162float(h));
}

// ---------------------------------------------------------------------------
// transpose + split (bf16 hi/lo): z=0 -> w_t1, z=1..3 -> w_i1 chunk z-1
// ---------------------------------------------------------------------------
__global__ void tsplit_w_k(const float* __restrict__ w1,
                           const float* __restrict__ wi1,
                           __nv_bfloat16* __restrict__ hi1, __nv_bfloat16* __restrict__ lo1,
                           __nv_bfloat16* __restrict__ hi2, __nv_bfloat16* __restrict__ lo2)
{
    const float* in; __nv_bfloat16 *hi, *lo;
    int z = blockIdx.z;
    if (z == 0) { in = w1; hi = hi1; lo = lo1; }
    else {
        in = wi1 + (long)(z - 1) * DD * HH;
        hi = hi2 + (long)(z - 1) * HH * DD;
        lo = lo2 + (long)(z - 1) * HH * DD;
    }
    __shared__ float t[32][33];
    int n0 = blockIdx.x * 32, k0 = blockIdx.y * 32;
    int n = n0 + threadIdx.x, k = k0 + threadIdx.y;
    t[threadIdx.y][threadIdx.x] = in[(long)k * HH + n];
    __syncthreads();
    int orow = n0 + threadIdx.y, ocol = k0 + threadIdx.x;
    float x = t[threadIdx.x][threadIdx.y];
    __nv_bfloat16 h = __float2bfloat16(x);
    hi[(long)orow * DD + ocol] = h;
    lo[(long)orow * DD + ocol] = __float2bfloat16(x - __bfloat162float(h));
}

// ---------------------------------------------------------------------------
// transpose, fp16 (w_t2)
// ---------------------------------------------------------------------------
__global__ void tsplit_h(const float* __restrict__ in, __half* __restrict__ hi,
                         int K, int N)
{
    __shared__ float t[32][33];
    int n0 = blockIdx.x * 32, k0 = blockIdx.y * 32;
    int n = n0 + threadIdx.x, k = k0 + threadIdx.y;
    t[threadIdx.y][threadIdx.x] = (n < N) ? in[(long)k * N + n] : 0.f;
    __syncthreads();
    int orow = n0 + threadIdx.y, ocol = k0 + threadIdx.x;
    hi[(long)orow * K + ocol] = __float2half_rn(t[threadIdx.x][threadIdx.y]);
}

// ---------------------------------------------------------------------------
// IoU combine + mask (mask folded in)
// ---------------------------------------------------------------------------
__global__ __launch_bounds__(192) void iou_mask_k(
    const float* __restrict__ P, const float* __restrict__ w2,
    const float* __restrict__ b2, float* __restrict__ out)
{
    const int idx = blockIdx.x;
    const int e = idx % 33;
    const int s = (idx / 33) % 32;
    const int b = idx / (33 * 32);
    const int c = (s + e) >> 1;
    const int t = threadIdx.x;

    // mask map: first 1056 blocks each write one element via thread 100
    if (t == 100 && idx < 32 * 33) {
        int i = idx / 33, j = idx % 33;
        float v = 0.f;
        int hi = (i + 17 < 33) ? (i + 17) : 33;
        if (j >= i + 1 && j < hi) v = 1.f;
        if (i < 16 && (i & 1) == 0 && j >= 18 + i && ((j - 18 - i) & 1) == 0) v = 1.f;
        out[OUT_MASK_BASE + idx] = v;
    }

    const long CS = (long)MPROJP * HH;
    const float4* ps = (const float4*)(P + (long)(b * 33 + s) * HH);
    const float4* pc = (const float4*)(P + CS + (long)(b * 33 + c) * HH);
    const float4* pe = (const float4*)(P + 2 * CS + (long)(b * 33 + e) * HH);
    const float4* wv = (const float4*)(w2) + t * 3;

    float4 a = ps[t], bb = pc[t], cc = pe[t];
    float v0 = fmaxf(a.x + bb.x + cc.x, 0.f);
    float v1 = fmaxf(a.y + bb.y + cc.y, 0.f);
    float v2 = fmaxf(a.z + bb.z + cc.z, 0.f);
    float v3 = fmaxf(a.w + bb.w + cc.w, 0.f);
    float4 w0 = wv[0], w1 = wv[1], w2v = wv[2];
    float k0 = v0 * w0.x + v1 * w0.w + v2 * w1.z + v3 * w2v.y;
    float k1 = v0 * w0.y + v1 * w1.x + v2 * w1.w + v3 * w2v.z;
    float k2 = v0 * w0.z + v1 * w1.y + v2 * w2v.x + v3 * w2v.w;

#pragma unroll
    for (int off = 16; off; off >>= 1) {
        k0 += __shfl_xor_sync(0xFFFFFFFFu, k0, off);
        k1 += __shfl_xor_sync(0xFFFFFFFFu, k1, off);
        k2 += __shfl_xor_sync(0xFFFFFFFFu, k2, off);
    }
    __shared__ float red[3][6];
    const int lane = t & 31, w = t >> 5;
    if (lane == 0) { red[0][w] = k0; red[1][w] = k1; red[2][w] = k2; }
    __syncthreads();
    if (t == 0) {
        float r0 = b2[0], r1 = b2[1], r2 = b2[2];
#pragma unroll
        for (int i = 0; i < 6; i++) { r0 += red[0][i]; r1 += red[1][i]; r2 += red[2][i]; }
        long base = OUT_IOU_BASE + ((long)b * 3) * (32 * 33) + (long)s * 33 + e;
        out[base + 0 * 32 * 33] = r0;
        out[base + 1 * 32 * 33] = r1;
        out[base + 2 * 32 * 33] = r2;
    }
}

// ---------------------------------------------------------------------------
extern "C" void kernel_launch(void* const* d_in, const int* in_sizes, int n_in,
                              void* d_out, int out_size)
{
    const float* ht   = (const float*)d_in[0];
    const float* hc   = (const float*)d_in[1];
    const float* w_t1 = (const float*)d_in[2];
    const float* b_t1 = (const float*)d_in[3];
    const float* w_t2 = (const float*)d_in[4];
    const float* b_t2 = (const float*)d_in[5];
    const float* w_i1 = (const float*)d_in[6];
    const float* b_i1 = (const float*)d_in[7];
    const float* w_i2 = (const float*)d_in[8];
    const float* b_i2 = (const float*)d_in[9];
    float* out = (float*)d_out;

    float* proj; cudaGetSymbolAddress((void**)&proj, g_proj);
    __nv_bfloat16 *Athi, *Atlo, *Achi, *Aclo;
    __nv_bfloat16 *Bw1hi, *Bw1lo, *Bi1hi, *Bi1lo;
    __half *H1hi, *H1lo, *Bw2hi;
    cudaGetSymbolAddress((void**)&Athi, g_Athi);
    cudaGetSymbolAddress((void**)&Atlo, g_Atlo);
    cudaGetSymbolAddress((void**)&Achi, g_Achi);
    cudaGetSymbolAddress((void**)&Aclo, g_Aclo);
    cudaGetSymbolAddress((void**)&H1hi, g_H1hi);
    cudaGetSymbolAddress((void**)&H1lo, g_H1lo);
    cudaGetSymbolAddress((void**)&Bw1hi, g_Bw1hi);
    cudaGetSymbolAddress((void**)&Bw1lo, g_Bw1lo);
    cudaGetSymbolAddress((void**)&Bi1hi, g_Bi1hi);
    cudaGetSymbolAddress((void**)&Bi1lo, g_Bi1lo);
    cudaGetSymbolAddress((void**)&Bw2hi, g_Bw2hi);

    cudaFuncSetAttribute(hgemm1,   cudaFuncAttributeMaxDynamicSharedMemorySize, 98304);
    cudaFuncSetAttribute(fat_gemm, cudaFuncAttributeMaxDynamicSharedMemorySize, 98304);

    // 1) splits of ht and hc
    {
        long n1 = (long)MTXT * DD, n2 = (long)MPROJ * DD;
        split_both_k<<<(int)((n1 + n2 + 255) / 256), 256>>>(
            ht, Athi, Atlo, n1, hc, Achi, Aclo, n2);
    }
    // 2) transpose+split w_t1 and w_i1
    tsplit_w_k<<<dim3(24, 24, 4), dim3(32, 32)>>>(w_t1, w_i1, Bw1hi, Bw1lo, Bi1hi, Bi1lo);
    // 3) transpose w_t2 (fp16)
    tsplit_h<<<dim3(NPAD / 32, 24), dim3(32, 32)>>>(w_t2, Bw2hi, DD, VV);
    // 4) GEMM1
    hgemm1<<<dim3(HH / 128, MTXT / 128), 256, 98304>>>(
        Athi, Atlo, Bw1hi, Bw1lo, b_t1, H1hi, H1lo);
    // 5) fat kernel: projections + vocab GEMM
    fat_gemm<<<PGRID + VGRID, 256, 98304>>>(
        H1hi, H1lo, Bw2hi, b_t2, out,
        Achi, Aclo, Bi1hi, Bi1lo, b_i1, proj);
    // 6) IoU combine + mask
    iou_mask_k<<<BB * TT * (TT + 1), 192>>>(proj, w_i2, b_i2, out);
}